// round 1
// baseline (speedup 1.0000x reference)
#include <cuda_runtime.h>
#include <math.h>

#define NN   100000
#define NE   500000
#define FEATD 128
#define HIDD  256
#define NL   16384

// ---------------- persistent scratch (device globals: no allocation allowed) ---
__device__ float g_deg[NN];
__device__ float g_h  [(size_t)NN * HIDD];
__device__ float g_agg[(size_t)NN * HIDD];
__device__ float g_h2 [(size_t)NN * HIDD];
__device__ int   g_is64;

// ---------------- index helpers (int32 vs int64 auto-detect) -------------------
__device__ __forceinline__ long long idx_at(const void* p, long long i, int is64) {
    if (is64) return ((const long long*)p)[i];
    return (long long)((const int*)p)[i];
}

__global__ void detect_kernel(const void* ei) {
    // If edge_index is int64 (values < 2^31), every odd 32-bit word is 0.
    // If int32, odd words are uniform random indices (P(0) ~ 1e-5).
    const unsigned* w = (const unsigned*)ei;
    int zeros = 0;
    for (int i = 1; i < 128; i += 2) zeros += (w[i] == 0u);
    g_is64 = (zeros >= 50) ? 1 : 0;
}

// ---------------- zero scratch ------------------------------------------------
__global__ void zero_kernel(int with_deg) {
    long long i = (long long)blockIdx.x * blockDim.x + threadIdx.x;
    if (i < (long long)NN * HIDD) g_agg[i] = 0.f;
    if (with_deg && i < NN)       g_deg[i] = 0.f;
}

// ---------------- in-degree ---------------------------------------------------
__global__ void deg_kernel(const void* ei) {
    int e = blockIdx.x * blockDim.x + threadIdx.x;
    if (e < NE) {
        long long d = idx_at(ei, (long long)NE + e, g_is64);
        atomicAdd(&g_deg[d], 1.f);
    }
}

// ---------------- edge aggregation: g_agg[dst] += h[src] ----------------------
// 4 edges / block, 64 threads (float4 lanes) per edge, vector RED to L2.
__global__ __launch_bounds__(256) void agg_kernel(const float* __restrict__ h,
                                                  const void* ei) {
    int e = blockIdx.x * 4 + (threadIdx.x >> 6);
    if (e >= NE) return;
    int lane = threadIdx.x & 63;
    int is64 = g_is64;
    long long s = idx_at(ei, e, is64);
    long long d = idx_at(ei, (long long)NE + e, is64);
    const float4 v = *(const float4*)(h + (int)s * HIDD + lane * 4);
    float* dp = g_agg + (int)d * HIDD + lane * 4;
    asm volatile("red.global.add.v4.f32 [%0], {%1,%2,%3,%4};"
                 :: "l"(dp), "f"(v.x), "f"(v.y), "f"(v.z), "f"(v.w)
                 : "memory");
}

// ---------------- tiled fp32 GEMMs -------------------------------------------
#define BM 128
#define BN 64
#define BK 32
// 256 threads: tx (0..15) -> 4 N-cols, ty (0..15) -> 8 M-rows.

// out[M,HID] = A[M,K] @ W[HID,K]^T + bias
__global__ __launch_bounds__(256) void embed_gemm(const float* __restrict__ A,
                                                  const float* __restrict__ W,
                                                  const float* __restrict__ bias,
                                                  float* __restrict__ out) {
    __shared__ float As[BM * 33];
    __shared__ float Bs[BK * 65];
    const int tid = threadIdx.x;
    const int tx = tid & 15, ty = tid >> 4;
    const int row0 = blockIdx.x * BM;
    const int n0   = blockIdx.y * BN;
    const int K = FEATD;

    float acc[8][4];
#pragma unroll
    for (int i = 0; i < 8; i++)
#pragma unroll
        for (int j = 0; j < 4; j++) acc[i][j] = 0.f;

    for (int k0 = 0; k0 < K; k0 += BK) {
#pragma unroll
        for (int t = 0; t < 16; t++) {           // A tile 128x32
            int lin = t * 256 + tid;
            int r = lin >> 5, kk = lin & 31;
            int row = row0 + r;
            As[r * 33 + kk] = (row < NN) ? A[(long long)row * K + k0 + kk] : 0.f;
        }
#pragma unroll
        for (int t = 0; t < 8; t++) {            // W tile 64x32
            int lin = t * 256 + tid;
            int n = lin >> 5, kk = lin & 31;
            Bs[kk * 65 + n] = W[(long long)(n0 + n) * K + k0 + kk];
        }
        __syncthreads();
#pragma unroll
        for (int kk = 0; kk < BK; kk++) {
            float a[8], b[4];
#pragma unroll
            for (int i = 0; i < 8; i++) a[i] = As[(ty * 8 + i) * 33 + kk];
#pragma unroll
            for (int j = 0; j < 4; j++) b[j] = Bs[kk * 65 + tx * 4 + j];
#pragma unroll
            for (int i = 0; i < 8; i++)
#pragma unroll
                for (int j = 0; j < 4; j++) acc[i][j] += a[i] * b[j];
        }
        __syncthreads();
    }
#pragma unroll
    for (int i = 0; i < 8; i++) {
        int row = row0 + ty * 8 + i;
        if (row < NN) {
#pragma unroll
            for (int j = 0; j < 4; j++) {
                int col = n0 + tx * 4 + j;
                out[(long long)row * HIDD + col] = acc[i][j] + bias[col];
            }
        }
    }
}

// out = relu( mean @ wl^T + bl + h @ wr^T ),  mean = (agg + h) * 1/(deg+1)
__global__ __launch_bounds__(256) void sage_gemm(const float* __restrict__ hin,
                                                 const float* __restrict__ wl,
                                                 const float* __restrict__ bl,
                                                 const float* __restrict__ wr,
                                                 float* __restrict__ out) {
    __shared__ float As[BM * 33];
    __shared__ float Bs[BK * 65];
    __shared__ float invd[BM];
    const int tid = threadIdx.x;
    const int tx = tid & 15, ty = tid >> 4;
    const int row0 = blockIdx.x * BM;
    const int n0   = blockIdx.y * BN;

    if (tid < BM) {
        int row = row0 + tid;
        invd[tid] = (row < NN) ? 1.f / (g_deg[row] + 1.f) : 0.f;
    }
    __syncthreads();

    float acc[8][4];
#pragma unroll
    for (int i = 0; i < 8; i++)
#pragma unroll
        for (int j = 0; j < 4; j++) acc[i][j] = 0.f;

    for (int phase = 0; phase < 2; phase++) {
        const float* W = phase ? wr : wl;
        for (int k0 = 0; k0 < HIDD; k0 += BK) {
#pragma unroll
            for (int t = 0; t < 16; t++) {       // A tile
                int lin = t * 256 + tid;
                int r = lin >> 5, kk = lin & 31;
                int row = row0 + r;
                float v = 0.f;
                if (row < NN) {
                    long long off = (long long)row * HIDD + k0 + kk;
                    v = phase ? hin[off] : (g_agg[off] + hin[off]) * invd[r];
                }
                As[r * 33 + kk] = v;
            }
#pragma unroll
            for (int t = 0; t < 8; t++) {        // W tile
                int lin = t * 256 + tid;
                int n = lin >> 5, kk = lin & 31;
                Bs[kk * 65 + n] = W[(long long)(n0 + n) * HIDD + k0 + kk];
            }
            __syncthreads();
#pragma unroll
            for (int kk = 0; kk < BK; kk++) {
                float a[8], b[4];
#pragma unroll
                for (int i = 0; i < 8; i++) a[i] = As[(ty * 8 + i) * 33 + kk];
#pragma unroll
                for (int j = 0; j < 4; j++) b[j] = Bs[kk * 65 + tx * 4 + j];
#pragma unroll
                for (int i = 0; i < 8; i++)
#pragma unroll
                    for (int j = 0; j < 4; j++) acc[i][j] += a[i] * b[j];
            }
            __syncthreads();
        }
    }
#pragma unroll
    for (int i = 0; i < 8; i++) {
        int row = row0 + ty * 8 + i;
        if (row < NN) {
#pragma unroll
            for (int j = 0; j < 4; j++) {
                int col = n0 + tx * 4 + j;
                float v = acc[i][j] + bl[col];
                out[(long long)row * HIDD + col] = fmaxf(v, 0.f);
            }
        }
    }
}

// ---------------- link prediction MLP ----------------------------------------
// 16 links / block, 256 threads; combined [16][1024] in dynamic smem.
#define LB 16
__global__ __launch_bounds__(256) void link_kernel(const float* __restrict__ h,
                                                   const void* srcp, const void* dstp,
                                                   const float* __restrict__ wp1,
                                                   const float* __restrict__ bp1,
                                                   const float* __restrict__ wp2,
                                                   const float* __restrict__ bp2,
                                                   float* __restrict__ out) {
    extern __shared__ float comb[];              // LB * 1024
    __shared__ float red[LB][9];
    const int tid = threadIdx.x;
    const int base = blockIdx.x * LB;
    const int is64 = g_is64;

    for (int t = tid; t < LB * HIDD; t += 256) {
        int l = t >> 8, k = t & 255;
        long long si = idx_at(srcp, base + l, is64);
        long long di = idx_at(dstp, base + l, is64);
        float sv = h[(int)si * HIDD + k];
        float dv = h[(int)di * HIDD + k];
        float* row = comb + l * 1024;
        row[k]        = sv;
        row[256 + k]  = dv;
        row[512 + k]  = sv * dv;
        row[768 + k]  = fabsf(sv - dv);
    }
    __syncthreads();

    float acc[LB];
#pragma unroll
    for (int l = 0; l < LB; l++) acc[l] = 0.f;

    const float* wrow = wp1 + tid * 1024;        // hidden unit `tid`
    for (int k = 0; k < 1024; k += 4) {
        float4 w4 = *(const float4*)(wrow + k);
#pragma unroll
        for (int l = 0; l < LB; l++) {
            float4 c4 = *(const float4*)(comb + l * 1024 + k);
            acc[l] += w4.x * c4.x + w4.y * c4.y + w4.z * c4.z + w4.w * c4.w;
        }
    }

    const float bj = bp1[tid];
    const float wj = wp2[tid];
    const int lane = tid & 31, wid = tid >> 5;
#pragma unroll
    for (int l = 0; l < LB; l++) {
        float v = fmaxf(acc[l] + bj, 0.f) * wj;
#pragma unroll
        for (int off = 16; off > 0; off >>= 1)
            v += __shfl_down_sync(0xffffffffu, v, off);
        if (lane == 0) red[l][wid] = v;
    }
    __syncthreads();
    if (tid < LB) {
        float s = 0.f;
#pragma unroll
        for (int w = 0; w < 8; w++) s += red[tid][w];
        s += bp2[0];
        out[base + tid] = 1.f / (1.f + expf(-s));
    }
}

// ---------------- launcher ----------------------------------------------------
extern "C" void kernel_launch(void* const* d_in, const int* in_sizes, int n_in,
                              void* d_out, int out_size) {
    (void)in_sizes; (void)n_in; (void)out_size;
    const float* x     = (const float*)d_in[0];
    const void*  ei    = d_in[1];
    // d_in[2] = edge_type (dead in reference)
    const void*  sidx  = d_in[3];
    const void*  didx  = d_in[4];
    const float* w_emb = (const float*)d_in[5];
    const float* b_emb = (const float*)d_in[6];
    // d_in[7] = edge_table (dead)
    const float* wl0 = (const float*)d_in[8];
    const float* bl0 = (const float*)d_in[9];
    const float* wr0 = (const float*)d_in[10];
    // d_in[11..12] = we0, be0 (dead)
    const float* wl1 = (const float*)d_in[13];
    const float* bl1 = (const float*)d_in[14];
    const float* wr1 = (const float*)d_in[15];
    // d_in[16..17] = we1, be1 (dead)
    const float* wp1 = (const float*)d_in[18];
    const float* bp1 = (const float*)d_in[19];
    const float* wp2 = (const float*)d_in[20];
    const float* bp2 = (const float*)d_in[21];
    float* out = (float*)d_out;

    cudaFuncSetAttribute(link_kernel, cudaFuncAttributeMaxDynamicSharedMemorySize,
                         LB * 1024 * (int)sizeof(float));

    const int zgrid = (NN * HIDD + 255) / 256;
    dim3 ggrid((NN + BM - 1) / BM, HIDD / BN);

    detect_kernel<<<1, 1>>>(ei);
    zero_kernel<<<zgrid, 256>>>(1);
    deg_kernel<<<(NE + 255) / 256, 256>>>(ei);
    embed_gemm<<<ggrid, 256>>>(x, w_emb, b_emb, g_h);

    agg_kernel<<<NE / 4, 256>>>(g_h, ei);
    sage_gemm<<<ggrid, 256>>>(g_h, wl0, bl0, wr0, g_h2);

    zero_kernel<<<zgrid, 256>>>(0);
    agg_kernel<<<NE / 4, 256>>>(g_h2, ei);
    sage_gemm<<<ggrid, 256>>>(g_h2, wl1, bl1, wr1, g_h);

    link_kernel<<<NL / LB, 256, LB * 1024 * sizeof(float)>>>(
        g_h, sidx, didx, wp1, bp1, wp2, bp2, out);
}

// round 6
// speedup vs baseline: 9.4024x; 9.4024x over previous
#include <cuda_runtime.h>
#include <cuda_bf16.h>
#include <math.h>
#include <stdint.h>

#define NN   100000
#define NE   500000
#define FEATD 128
#define HIDD  256
#define NL   16384

// ---------------- persistent scratch ------------------------------------------
__device__ float g_deg[NN];
__device__ float g_h  [(size_t)NN * HIDD];
__device__ float g_agg[(size_t)NN * HIDD];
__device__ float g_h2 [(size_t)NN * HIDD];
__device__ float g_comb[(size_t)NL * 4 * HIDD];
__device__ float g_lacc[NL];
__device__ int   g_is64;

// bf16 split weights (hi / lo)
__device__ __nv_bfloat16 g_wembH[HIDD*FEATD], g_wembL[HIDD*FEATD];
__device__ __nv_bfloat16 g_wl0H[HIDD*HIDD],   g_wl0L[HIDD*HIDD];
__device__ __nv_bfloat16 g_wr0H[HIDD*HIDD],   g_wr0L[HIDD*HIDD];
__device__ __nv_bfloat16 g_wl1H[HIDD*HIDD],   g_wl1L[HIDD*HIDD];
__device__ __nv_bfloat16 g_wr1H[HIDD*HIDD],   g_wr1L[HIDD*HIDD];
__device__ __nv_bfloat16 g_wp1H[HIDD*4*HIDD], g_wp1L[HIDD*4*HIDD];

// ---------------- helpers -------------------------------------------------------
__device__ __forceinline__ uint32_t smem_u32(const void* p) {
    uint32_t a;
    asm("{ .reg .u64 t; cvta.to.shared.u64 t, %1; cvt.u32.u64 %0, t; }"
        : "=r"(a) : "l"(p));
    return a;
}
static __device__ __forceinline__ uint32_t swz(uint32_t x) {
    return x ^ ((x >> 3) & 0x70);
}
__device__ __forceinline__ void split2(float a, float b, uint32_t& hi, uint32_t& lo) {
    __nv_bfloat16 ha = __float2bfloat16(a), hb = __float2bfloat16(b);
    float fa = __bfloat162float(ha), fb = __bfloat162float(hb);
    __nv_bfloat16 la = __float2bfloat16(a - fa), lb = __float2bfloat16(b - fb);
    hi = ((uint32_t)__bfloat16_as_ushort(hb) << 16) | __bfloat16_as_ushort(ha);
    lo = ((uint32_t)__bfloat16_as_ushort(lb) << 16) | __bfloat16_as_ushort(la);
}
__device__ __forceinline__ long long idx_at(const void* p, long long i, int is64) {
    if (is64) return ((const long long*)p)[i];
    return (long long)((const int*)p)[i];
}

__device__ __forceinline__ void ldmx4(uint32_t* r, uint32_t a) {
    asm volatile("ldmatrix.sync.aligned.m8n8.x4.shared.b16 {%0,%1,%2,%3}, [%4];"
                 : "=r"(r[0]), "=r"(r[1]), "=r"(r[2]), "=r"(r[3]) : "r"(a));
}
__device__ __forceinline__ void ldmx2(uint32_t* r, uint32_t a) {
    asm volatile("ldmatrix.sync.aligned.m8n8.x2.shared.b16 {%0,%1}, [%2];"
                 : "=r"(r[0]), "=r"(r[1]) : "r"(a));
}
#define MMA_BF16(d, a, b) \
    asm volatile("mma.sync.aligned.m16n8k16.row.col.f32.bf16.bf16.f32 " \
        "{%0,%1,%2,%3}, {%4,%5,%6,%7}, {%8,%9}, {%0,%1,%2,%3};" \
        : "+f"((d)[0]), "+f"((d)[1]), "+f"((d)[2]), "+f"((d)[3]) \
        : "r"((a)[0]), "r"((a)[1]), "r"((a)[2]), "r"((a)[3]), \
          "r"((b)[0]), "r"((b)[1]))

// ---------------- misc small kernels -------------------------------------------
__global__ void detect_kernel(const void* ei) {
    const unsigned* w = (const unsigned*)ei;
    int zeros = 0;
    for (int i = 1; i < 128; i += 2) zeros += (w[i] == 0u);
    g_is64 = (zeros >= 50) ? 1 : 0;
}

__global__ void zero_kernel(int with_deg) {
    long long i = (long long)blockIdx.x * blockDim.x + threadIdx.x;
    if (i < (long long)NN * HIDD) g_agg[i] = 0.f;
    if (with_deg && i < NN)       g_deg[i] = 0.f;
    if (with_deg && i < NL)       g_lacc[i] = 0.f;
}

__global__ void deg_kernel(const void* ei) {
    int e = blockIdx.x * blockDim.x + threadIdx.x;
    if (e < NE) {
        long long d = idx_at(ei, (long long)NE + e, g_is64);
        atomicAdd(&g_deg[d], 1.f);
    }
}

__global__ __launch_bounds__(256) void agg_kernel(const float* __restrict__ h,
                                                  const void* ei) {
    int e = blockIdx.x * 4 + (threadIdx.x >> 6);
    if (e >= NE) return;
    int lane = threadIdx.x & 63;
    int is64 = g_is64;
    long long s = idx_at(ei, e, is64);
    long long d = idx_at(ei, (long long)NE + e, is64);
    const float4 v = *(const float4*)(h + (size_t)s * HIDD + lane * 4);
    float* dp = g_agg + (size_t)d * HIDD + lane * 4;
    asm volatile("red.global.add.v4.f32 [%0], {%1,%2,%3,%4};"
                 :: "l"(dp), "f"(v.x), "f"(v.y), "f"(v.z), "f"(v.w) : "memory");
}

__global__ void wconv_kernel(const float* __restrict__ w,
                             __nv_bfloat16* __restrict__ hi,
                             __nv_bfloat16* __restrict__ lo, int n) {
    int i = blockIdx.x * 256 + threadIdx.x;
    if (i < n) {
        float v = w[i];
        __nv_bfloat16 h = __float2bfloat16(v);
        hi[i] = h;
        lo[i] = __float2bfloat16(v - __bfloat162float(h));
    }
}

__global__ __launch_bounds__(256) void comb_kernel(const float* __restrict__ h,
                                                   const void* sp, const void* dp) {
    int t = blockIdx.x * 256 + threadIdx.x;   // NL*64 total
    int l = t >> 6, q = t & 63;
    int is64 = g_is64;
    long long si = idx_at(sp, l, is64);
    long long di = idx_at(dp, l, is64);
    float4 s4 = *(const float4*)(h + (size_t)si * HIDD + q * 4);
    float4 d4 = *(const float4*)(h + (size_t)di * HIDD + q * 4);
    float* row = g_comb + (size_t)l * 1024;
    *(float4*)(row + q * 4)       = s4;
    *(float4*)(row + 256 + q * 4) = d4;
    *(float4*)(row + 512 + q * 4) = make_float4(s4.x*d4.x, s4.y*d4.y, s4.z*d4.z, s4.w*d4.w);
    *(float4*)(row + 768 + q * 4) = make_float4(fabsf(s4.x-d4.x), fabsf(s4.y-d4.y),
                                                fabsf(s4.z-d4.z), fabsf(s4.w-d4.w));
}

__global__ void linkfin_kernel(const float* __restrict__ bp2, float* __restrict__ out) {
    int i = blockIdx.x * 256 + threadIdx.x;
    if (i < NL) out[i] = 1.f / (1.f + expf(-(g_lacc[i] + bp2[0])));
}

// ---------------- mma.sync split-bf16 GEMM --------------------------------------
// D[128,128-slice] = A[128,K] @ W[256,K]^T  via 3 bf16 products, fp32 accum regs.
// MODE 0: embed (K=128, out = D + bias)
// MODE 1: sage  (K=2x256: mean@wl^T + h@wr^T; out = relu(D + bias))
// MODE 2: link  (K=1024; epilogue: atomicAdd(relu(D+bp1).wp2) per row)

#define SA_H   0
#define SA_L   16384
#define SW_H   32768
#define SW_L   49152
#define S_MISC 65536
#define SMEMB  (S_MISC + 512 + 1024)

template <int MODE>
__global__ __launch_bounds__(256) void gemm_tc(
    const float* __restrict__ A, const float* __restrict__ Aagg,
    const __nv_bfloat16* __restrict__ W1H, const __nv_bfloat16* __restrict__ W1L,
    const __nv_bfloat16* __restrict__ W2H, const __nv_bfloat16* __restrict__ W2L,
    const float* __restrict__ bias, const float* __restrict__ wp2,
    float* __restrict__ outp)
{
    extern __shared__ char smraw[];
    char* smc = (char*)(((uintptr_t)smraw + 1023) & ~(uintptr_t)1023);
    const uint32_t sbase = smem_u32(smc);
    const int tid = threadIdx.x;
    const int wid = tid >> 5, l = tid & 31;
    const int wm = wid >> 1, wn = wid & 1;       // 4 x 2 warp grid
    const int row0 = blockIdx.x * 128;
    const int n0   = blockIdx.y * 128;

    constexpr int NCH = (MODE == 0) ? 2 : (MODE == 1) ? 8 : 16;
    constexpr int KA  = (MODE == 0) ? FEATD : (MODE == 1) ? HIDD : 1024;

    float* invd_s = (float*)(smc + S_MISC);
    if (MODE == 1 && tid < 128) {
        int row = row0 + tid;
        invd_s[tid] = (row < NN) ? 1.f / (g_deg[row] + 1.f) : 0.f;
    }
    if (MODE == 1) __syncthreads();

    float acc[2][8][4];
#pragma unroll
    for (int mt = 0; mt < 2; mt++)
#pragma unroll
        for (int nt = 0; nt < 8; nt++)
#pragma unroll
            for (int j = 0; j < 4; j++) acc[mt][nt][j] = 0.f;

    const int ar  = tid >> 1;             // A row 0..127
    const int ac0 = (tid & 1) * 32;       // A col half
    const bool avalid = (MODE == 2) || (row0 + ar < NN);
    const int wr  = tid >> 1;             // W row 0..127 (local)
    const int wc0 = (tid & 1) * 32;

    for (int c = 0; c < NCH; c++) {
        const int colbase = (MODE == 1) ? ((c & 3) * 64) : (c * 64);

        // ---- A tile: 128 x 64 fp32 -> bf16 hi/lo, swizzled ----
        {
            const size_t abase = (size_t)(row0 + ar) * KA + colbase + ac0;
#pragma unroll
            for (int i = 0; i < 8; i++) {
                float4 v = make_float4(0.f, 0.f, 0.f, 0.f);
                if (avalid) {
                    if (MODE == 1) {
                        float4 hv = *(const float4*)(A + abase + i * 4);
                        if (c < 4) {
                            float4 av = *(const float4*)(Aagg + abase + i * 4);
                            float iv = invd_s[ar];
                            v = make_float4((av.x + hv.x) * iv, (av.y + hv.y) * iv,
                                            (av.z + hv.z) * iv, (av.w + hv.w) * iv);
                        } else v = hv;
                    } else {
                        v = *(const float4*)(A + abase + i * 4);
                    }
                }
                uint32_t h0, l0, h1, l1;
                split2(v.x, v.y, h0, l0);
                split2(v.z, v.w, h1, l1);
                uint32_t s = swz(ar * 128 + (ac0 + i * 4) * 2);
                *(uint2*)(smc + SA_H + s) = make_uint2(h0, h1);
                *(uint2*)(smc + SA_L + s) = make_uint2(l0, l1);
            }
        }
        // ---- W tile: 128 (this CTA's n-half) x 64 bf16 hi/lo, swizzled ----
        {
            const __nv_bfloat16* WH = (MODE == 1 && c >= 4) ? W2H : W1H;
            const __nv_bfloat16* WL = (MODE == 1 && c >= 4) ? W2L : W1L;
            const size_t wbase = (size_t)(n0 + wr) * KA + colbase + wc0;
#pragma unroll
            for (int j = 0; j < 4; j++) {
                uint4 hv = *(const uint4*)(WH + wbase + j * 8);
                uint4 lv = *(const uint4*)(WL + wbase + j * 8);
                uint32_t s = swz(wr * 128 + (wc0 + j * 8) * 2);
                *(uint4*)(smc + SW_H + s) = hv;
                *(uint4*)(smc + SW_L + s) = lv;
            }
        }
        __syncthreads();

        // ---- mma phase: 3 split products over this K=64 chunk ----
        for (int kk = 0; kk < 4; kk++) {
            const uint32_t kbyte = kk * 32;
            uint32_t ah[2][4], alo[2][4];
#pragma unroll
            for (int mt = 0; mt < 2; mt++) {
                uint32_t off = swz((wm * 32 + mt * 16 + (l & 15)) * 128 +
                                   kbyte + ((l >> 4) << 4));
                ldmx4(ah[mt],  sbase + SA_H + off);
                ldmx4(alo[mt], sbase + SA_L + off);
            }
            const uint32_t cbB = kbyte + (((l >> 3) & 1) << 4);
            const uint32_t nbB = (wn * 64 + (l & 7)) * 128;
#pragma unroll
            for (int nt = 0; nt < 8; nt++) {
                uint32_t off = swz(nbB + nt * 8 * 128 + cbB);
                uint32_t bh[2], bl[2];
                ldmx2(bh, sbase + SW_H + off);
                ldmx2(bl, sbase + SW_L + off);
#pragma unroll
                for (int mt = 0; mt < 2; mt++) {
                    MMA_BF16(acc[mt][nt], ah[mt],  bh);
                    MMA_BF16(acc[mt][nt], ah[mt],  bl);
                    MMA_BF16(acc[mt][nt], alo[mt], bh);
                }
            }
        }
        __syncthreads();
    }

    // ---- epilogue ----
    if (MODE == 2) {
#pragma unroll
        for (int mt = 0; mt < 2; mt++) {
            int rloc = wm * 32 + mt * 16 + (l >> 2);
            float s0 = 0.f, s1 = 0.f;
#pragma unroll
            for (int nt = 0; nt < 8; nt++) {
                int col = n0 + wn * 64 + nt * 8 + (l & 3) * 2;
                float b0 = bias[col], b1 = bias[col + 1];
                float w0 = wp2[col],  w1 = wp2[col + 1];
                s0 += fmaxf(acc[mt][nt][0] + b0, 0.f) * w0
                    + fmaxf(acc[mt][nt][1] + b1, 0.f) * w1;
                s1 += fmaxf(acc[mt][nt][2] + b0, 0.f) * w0
                    + fmaxf(acc[mt][nt][3] + b1, 0.f) * w1;
            }
            atomicAdd(&g_lacc[row0 + rloc], s0);
            atomicAdd(&g_lacc[row0 + rloc + 8], s1);
        }
    } else {
#pragma unroll
        for (int mt = 0; mt < 2; mt++) {
            int r0 = row0 + wm * 32 + mt * 16 + (l >> 2);
#pragma unroll
            for (int nt = 0; nt < 8; nt++) {
                int col = n0 + wn * 64 + nt * 8 + (l & 3) * 2;
                float b0 = bias[col], b1 = bias[col + 1];
                float v0 = acc[mt][nt][0] + b0, v1 = acc[mt][nt][1] + b1;
                float v2 = acc[mt][nt][2] + b0, v3 = acc[mt][nt][3] + b1;
                if (MODE == 1) {
                    v0 = fmaxf(v0, 0.f); v1 = fmaxf(v1, 0.f);
                    v2 = fmaxf(v2, 0.f); v3 = fmaxf(v3, 0.f);
                }
                if (r0 < NN) {
                    float2 o = make_float2(v0, v1);
                    *(float2*)(outp + (size_t)r0 * HIDD + col) = o;
                }
                if (r0 + 8 < NN) {
                    float2 o = make_float2(v2, v3);
                    *(float2*)(outp + (size_t)(r0 + 8) * HIDD + col) = o;
                }
            }
        }
    }
}

// ---------------- launcher ------------------------------------------------------
extern "C" void kernel_launch(void* const* d_in, const int* in_sizes, int n_in,
                              void* d_out, int out_size) {
    (void)in_sizes; (void)n_in; (void)out_size;
    const float* x     = (const float*)d_in[0];
    const void*  ei    = d_in[1];
    const void*  sidx  = d_in[3];
    const void*  didx  = d_in[4];
    const float* w_emb = (const float*)d_in[5];
    const float* b_emb = (const float*)d_in[6];
    const float* wl0 = (const float*)d_in[8];
    const float* bl0 = (const float*)d_in[9];
    const float* wr0 = (const float*)d_in[10];
    const float* wl1 = (const float*)d_in[13];
    const float* bl1 = (const float*)d_in[14];
    const float* wr1 = (const float*)d_in[15];
    const float* wp1 = (const float*)d_in[18];
    const float* bp1 = (const float*)d_in[19];
    const float* wp2 = (const float*)d_in[20];
    const float* bp2 = (const float*)d_in[21];
    float* out = (float*)d_out;

    cudaFuncSetAttribute(gemm_tc<0>, cudaFuncAttributeMaxDynamicSharedMemorySize, SMEMB);
    cudaFuncSetAttribute(gemm_tc<1>, cudaFuncAttributeMaxDynamicSharedMemorySize, SMEMB);
    cudaFuncSetAttribute(gemm_tc<2>, cudaFuncAttributeMaxDynamicSharedMemorySize, SMEMB);

    __nv_bfloat16 *wembH, *wembL, *wl0H, *wl0L, *wr0H, *wr0L,
                  *wl1H, *wl1L, *wr1H, *wr1L, *wp1H, *wp1L;
    float *hbuf, *aggbuf, *h2buf, *combbuf;
    cudaGetSymbolAddress((void**)&wembH, g_wembH);
    cudaGetSymbolAddress((void**)&wembL, g_wembL);
    cudaGetSymbolAddress((void**)&wl0H, g_wl0H);
    cudaGetSymbolAddress((void**)&wl0L, g_wl0L);
    cudaGetSymbolAddress((void**)&wr0H, g_wr0H);
    cudaGetSymbolAddress((void**)&wr0L, g_wr0L);
    cudaGetSymbolAddress((void**)&wl1H, g_wl1H);
    cudaGetSymbolAddress((void**)&wl1L, g_wl1L);
    cudaGetSymbolAddress((void**)&wr1H, g_wr1H);
    cudaGetSymbolAddress((void**)&wr1L, g_wr1L);
    cudaGetSymbolAddress((void**)&wp1H, g_wp1H);
    cudaGetSymbolAddress((void**)&wp1L, g_wp1L);
    cudaGetSymbolAddress((void**)&hbuf, g_h);
    cudaGetSymbolAddress((void**)&aggbuf, g_agg);
    cudaGetSymbolAddress((void**)&h2buf, g_h2);
    cudaGetSymbolAddress((void**)&combbuf, g_comb);

    const int zgrid = (NN * HIDD + 255) / 256;
    dim3 ggrid((NN + 127) / 128, 2);         // 782 x 2
    dim3 lgrid(NL / 128, 2);                 // 128 x 2

    detect_kernel<<<1, 1>>>(ei);
    wconv_kernel<<<(HIDD*FEATD + 255)/256, 256>>>(w_emb, wembH, wembL, HIDD*FEATD);
    wconv_kernel<<<(HIDD*HIDD + 255)/256, 256>>>(wl0, wl0H, wl0L, HIDD*HIDD);
    wconv_kernel<<<(HIDD*HIDD + 255)/256, 256>>>(wr0, wr0H, wr0L, HIDD*HIDD);
    wconv_kernel<<<(HIDD*HIDD + 255)/256, 256>>>(wl1, wl1H, wl1L, HIDD*HIDD);
    wconv_kernel<<<(HIDD*HIDD + 255)/256, 256>>>(wr1, wr1H, wr1L, HIDD*HIDD);
    wconv_kernel<<<(HIDD*4*HIDD + 255)/256, 256>>>(wp1, wp1H, wp1L, HIDD*4*HIDD);

    zero_kernel<<<zgrid, 256>>>(1);
    deg_kernel<<<(NE + 255)/256, 256>>>(ei);

    gemm_tc<0><<<ggrid, 256, SMEMB>>>(x, nullptr, wembH, wembL, nullptr, nullptr,
                                      b_emb, nullptr, hbuf);

    agg_kernel<<<NE/4, 256>>>(hbuf, ei);
    gemm_tc<1><<<ggrid, 256, SMEMB>>>(hbuf, aggbuf, wl0H, wl0L, wr0H, wr0L,
                                      bl0, nullptr, h2buf);

    zero_kernel<<<zgrid, 256>>>(0);
    agg_kernel<<<NE/4, 256>>>(h2buf, ei);
    gemm_tc<1><<<ggrid, 256, SMEMB>>>(h2buf, aggbuf, wl1H, wl1L, wr1H, wr1L,
                                      bl1, nullptr, hbuf);

    comb_kernel<<<NL*64/256, 256>>>(hbuf, sidx, didx);
    gemm_tc<2><<<lgrid, 256, SMEMB>>>(combbuf, nullptr, wp1H, wp1L, nullptr, nullptr,
                                      bp1, wp2, nullptr);
    linkfin_kernel<<<NL/256, 256>>>(bp2, out);
}

// round 7
// speedup vs baseline: 11.8693x; 1.2624x over previous
#include <cuda_runtime.h>
#include <cuda_fp16.h>
#include <math.h>
#include <stdint.h>

#define NN   100000
#define NE   500000
#define FEATD 128
#define HIDD  256
#define NL   16384

// ---------------- persistent scratch ------------------------------------------
__device__ float g_deg[NN];
__device__ float g_h  [(size_t)NN * HIDD];
__device__ float g_agg[(size_t)NN * HIDD];
__device__ float g_h2 [(size_t)NN * HIDD];
__device__ float g_comb[(size_t)NL * 4 * HIDD];
__device__ float g_lacc[NL];
__device__ int   g_is64;

// fp16 weights (plain, not split — A is the split operand)
__device__ __half g_wembC[HIDD*FEATD];
__device__ __half g_wl0C[HIDD*HIDD];
__device__ __half g_wr0C[HIDD*HIDD];
__device__ __half g_wl1C[HIDD*HIDD];
__device__ __half g_wr1C[HIDD*HIDD];
__device__ __half g_wp1C[HIDD*4*HIDD];

// ---------------- helpers -------------------------------------------------------
__device__ __forceinline__ uint32_t smem_u32(const void* p) {
    uint32_t a;
    asm("{ .reg .u64 t; cvta.to.shared.u64 t, %1; cvt.u32.u64 %0, t; }"
        : "=r"(a) : "l"(p));
    return a;
}
static __device__ __forceinline__ uint32_t swz(uint32_t x) {
    return x ^ ((x >> 3) & 0x70);
}
// fp16 split: v = hi + lo (each fp16), packed as f16x2 words
__device__ __forceinline__ void split2h(float a, float b, uint32_t& hi, uint32_t& lo) {
    __half ha = __float2half(a), hb = __float2half(b);
    __half la = __float2half(a - __half2float(ha));
    __half lb = __float2half(b - __half2float(hb));
    hi = ((uint32_t)__half_as_ushort(hb) << 16) | __half_as_ushort(ha);
    lo = ((uint32_t)__half_as_ushort(lb) << 16) | __half_as_ushort(la);
}
__device__ __forceinline__ long long idx_at(const void* p, long long i, int is64) {
    if (is64) return ((const long long*)p)[i];
    return (long long)((const int*)p)[i];
}
__device__ __forceinline__ void ldmx4(uint32_t* r, uint32_t a) {
    asm volatile("ldmatrix.sync.aligned.m8n8.x4.shared.b16 {%0,%1,%2,%3}, [%4];"
                 : "=r"(r[0]), "=r"(r[1]), "=r"(r[2]), "=r"(r[3]) : "r"(a));
}
#define MMA_F16(d, a, b) \
    asm volatile("mma.sync.aligned.m16n8k16.row.col.f32.f16.f16.f32 " \
        "{%0,%1,%2,%3}, {%4,%5,%6,%7}, {%8,%9}, {%0,%1,%2,%3};" \
        : "+f"((d)[0]), "+f"((d)[1]), "+f"((d)[2]), "+f"((d)[3]) \
        : "r"((a)[0]), "r"((a)[1]), "r"((a)[2]), "r"((a)[3]), \
          "r"((b)[0]), "r"((b)[1]))

// ---------------- prep: detect + all weight conversions (1 launch) --------------
__global__ void prep_kernel(const void* ei,
                            const float* __restrict__ wemb,
                            const float* __restrict__ wl0, const float* __restrict__ wr0,
                            const float* __restrict__ wl1, const float* __restrict__ wr1,
                            const float* __restrict__ wp1) {
    int i = blockIdx.x * 256 + threadIdx.x;
    if (i == 0) {
        const unsigned* w = (const unsigned*)ei;
        int zeros = 0;
        for (int j = 1; j < 128; j += 2) zeros += (w[j] == 0u);
        g_is64 = (zeros >= 50) ? 1 : 0;
    }
    if (i < 32768)       g_wembC[i]          = __float2half(wemb[i]);
    else if (i < 98304)  g_wl0C[i - 32768]   = __float2half(wl0[i - 32768]);
    else if (i < 163840) g_wr0C[i - 98304]   = __float2half(wr0[i - 98304]);
    else if (i < 229376) g_wl1C[i - 163840]  = __float2half(wl1[i - 163840]);
    else if (i < 294912) g_wr1C[i - 229376]  = __float2half(wr1[i - 229376]);
    else if (i < 557056) g_wp1C[i - 294912]  = __float2half(wp1[i - 294912]);
}

// ---------------- misc small kernels -------------------------------------------
__global__ void zero_kernel(int with_deg) {
    long long i = (long long)blockIdx.x * blockDim.x + threadIdx.x;
    if (i < (long long)NN * HIDD) g_agg[i] = 0.f;
    if (with_deg && i < NN)       g_deg[i] = 0.f;
    if (with_deg && i < NL)       g_lacc[i] = 0.f;
}

__global__ void deg_kernel(const void* ei) {
    int e = blockIdx.x * blockDim.x + threadIdx.x;
    if (e < NE) {
        long long d = idx_at(ei, (long long)NE + e, g_is64);
        atomicAdd(&g_deg[d], 1.f);
    }
}

__global__ __launch_bounds__(256) void agg_kernel(const float* __restrict__ h,
                                                  const void* ei) {
    int e = blockIdx.x * 4 + (threadIdx.x >> 6);
    if (e >= NE) return;
    int lane = threadIdx.x & 63;
    int is64 = g_is64;
    long long s = idx_at(ei, e, is64);
    long long d = idx_at(ei, (long long)NE + e, is64);
    const float4 v = *(const float4*)(h + (size_t)s * HIDD + lane * 4);
    float* dp = g_agg + (size_t)d * HIDD + lane * 4;
    asm volatile("red.global.add.v4.f32 [%0], {%1,%2,%3,%4};"
                 :: "l"(dp), "f"(v.x), "f"(v.y), "f"(v.z), "f"(v.w) : "memory");
}

__global__ __launch_bounds__(256) void comb_kernel(const float* __restrict__ h,
                                                   const void* sp, const void* dp) {
    int t = blockIdx.x * 256 + threadIdx.x;   // NL*64 total
    int l = t >> 6, q = t & 63;
    int is64 = g_is64;
    long long si = idx_at(sp, l, is64);
    long long di = idx_at(dp, l, is64);
    float4 s4 = *(const float4*)(h + (size_t)si * HIDD + q * 4);
    float4 d4 = *(const float4*)(h + (size_t)di * HIDD + q * 4);
    float* row = g_comb + (size_t)l * 1024;
    *(float4*)(row + q * 4)       = s4;
    *(float4*)(row + 256 + q * 4) = d4;
    *(float4*)(row + 512 + q * 4) = make_float4(s4.x*d4.x, s4.y*d4.y, s4.z*d4.z, s4.w*d4.w);
    *(float4*)(row + 768 + q * 4) = make_float4(fabsf(s4.x-d4.x), fabsf(s4.y-d4.y),
                                                fabsf(s4.z-d4.z), fabsf(s4.w-d4.w));
}

__global__ void linkfin_kernel(const float* __restrict__ bp2, float* __restrict__ out) {
    int i = blockIdx.x * 256 + threadIdx.x;
    if (i < NL) out[i] = 1.f / (1.f + expf(-(g_lacc[i] + bp2[0])));
}

// ---------------- mma.sync split-fp16 GEMM --------------------------------------
// D[128,128-slice] = A[128,K] @ W[256,K]^T,  2 products: Ah*W + Al*W (W plain fp16)
// MODE 0: embed (K=128, out = D + bias)
// MODE 1: sage  (K=2x256: mean@wl^T + h@wr^T; out = relu(D + bias))
// MODE 2: link  (K=1024; epilogue: atomicAdd(relu(D+bp1).wp2) per row)

#define SA_H   0
#define SA_L   16384
#define SW_    32768
#define S_MISC 49152
#define SMEMB  (S_MISC + 512 + 1024)

template <int MODE>
__global__ __launch_bounds__(256, 2) void gemm_tc(
    const float* __restrict__ A, const float* __restrict__ Aagg,
    const __half* __restrict__ W1, const __half* __restrict__ W2,
    const float* __restrict__ bias, const float* __restrict__ wp2,
    float* __restrict__ outp)
{
    extern __shared__ char smraw[];
    char* smc = (char*)(((uintptr_t)smraw + 1023) & ~(uintptr_t)1023);
    const uint32_t sbase = smem_u32(smc);
    const int tid = threadIdx.x;
    const int wid = tid >> 5, l = tid & 31;
    const int wm = wid >> 1, wn = wid & 1;       // 4 x 2 warp grid
    const int row0 = blockIdx.x * 128;
    const int n0   = blockIdx.y * 128;

    constexpr int NCH = (MODE == 0) ? 2 : (MODE == 1) ? 8 : 16;
    constexpr int KA  = (MODE == 0) ? FEATD : (MODE == 1) ? HIDD : 1024;

    float* invd_s = (float*)(smc + S_MISC);
    if (MODE == 1 && tid < 128) {
        int row = row0 + tid;
        invd_s[tid] = (row < NN) ? 1.f / (g_deg[row] + 1.f) : 0.f;
    }
    if (MODE == 1) __syncthreads();

    float acc[2][8][4];
#pragma unroll
    for (int mt = 0; mt < 2; mt++)
#pragma unroll
        for (int nt = 0; nt < 8; nt++)
#pragma unroll
            for (int j = 0; j < 4; j++) acc[mt][nt][j] = 0.f;

    const int ar  = tid >> 1;             // A row 0..127
    const int ac0 = (tid & 1) * 32;       // A col half
    const bool avalid = (MODE == 2) || (row0 + ar < NN);
    const int wr  = tid >> 1;             // W row 0..127 (local)
    const int wc0 = (tid & 1) * 32;

    for (int c = 0; c < NCH; c++) {
        const int colbase = (MODE == 1) ? ((c & 3) * 64) : (c * 64);

        // ---- A tile: 128 x 64 fp32 -> fp16 hi/lo, swizzled ----
        {
            const size_t abase = (size_t)(row0 + ar) * KA + colbase + ac0;
#pragma unroll
            for (int i = 0; i < 8; i++) {
                float4 v = make_float4(0.f, 0.f, 0.f, 0.f);
                if (avalid) {
                    if (MODE == 1) {
                        float4 hv = *(const float4*)(A + abase + i * 4);
                        if (c < 4) {
                            float4 av = *(const float4*)(Aagg + abase + i * 4);
                            float iv = invd_s[ar];
                            v = make_float4((av.x + hv.x) * iv, (av.y + hv.y) * iv,
                                            (av.z + hv.z) * iv, (av.w + hv.w) * iv);
                        } else v = hv;
                    } else {
                        v = *(const float4*)(A + abase + i * 4);
                    }
                }
                uint32_t h0, l0, h1, l1;
                split2h(v.x, v.y, h0, l0);
                split2h(v.z, v.w, h1, l1);
                uint32_t s = swz(ar * 128 + (ac0 + i * 4) * 2);
                *(uint2*)(smc + SA_H + s) = make_uint2(h0, h1);
                *(uint2*)(smc + SA_L + s) = make_uint2(l0, l1);
            }
        }
        // ---- W tile: 128 (this CTA's n-half) x 64 fp16, swizzled ----
        {
            const __half* W = (MODE == 1 && c >= 4) ? W2 : W1;
            const size_t wbase = (size_t)(n0 + wr) * KA + colbase + wc0;
#pragma unroll
            for (int j = 0; j < 4; j++) {
                uint4 hv = *(const uint4*)(W + wbase + j * 8);
                *(uint4*)(smc + SW_ + swz(wr * 128 + (wc0 + j * 8) * 2)) = hv;
            }
        }
        __syncthreads();

        // ---- mma phase: 2 products over this K=64 chunk ----
#pragma unroll
        for (int kk = 0; kk < 4; kk++) {
            const uint32_t kbyte = kk * 32;
            uint32_t ah[2][4], al[2][4];
#pragma unroll
            for (int mt = 0; mt < 2; mt++) {
                uint32_t off = swz((wm * 32 + mt * 16 + (l & 15)) * 128 +
                                   kbyte + ((l >> 4) << 4));
                ldmx4(ah[mt], sbase + SA_H + off);
                ldmx4(al[mt], sbase + SA_L + off);
            }
            uint32_t bf[8][2];
#pragma unroll
            for (int ntb = 0; ntb < 4; ntb++) {
                const int nt2 = ntb * 2;
                uint32_t off = swz((wn * 64 + (nt2 + ((l >> 4) & 1)) * 8 + (l & 7)) * 128
                                   + kbyte + (((l >> 3) & 1) << 4));
                uint32_t r[4];
                ldmx4(r, sbase + SW_ + off);
                bf[nt2][0] = r[0]; bf[nt2][1] = r[1];
                bf[nt2 + 1][0] = r[2]; bf[nt2 + 1][1] = r[3];
            }
#pragma unroll
            for (int nt = 0; nt < 8; nt++)
#pragma unroll
                for (int mt = 0; mt < 2; mt++) {
                    MMA_F16(acc[mt][nt], ah[mt], bf[nt]);
                    MMA_F16(acc[mt][nt], al[mt], bf[nt]);
                }
        }
        __syncthreads();
    }

    // ---- epilogue ----
    if (MODE == 2) {
#pragma unroll
        for (int mt = 0; mt < 2; mt++) {
            int rloc = wm * 32 + mt * 16 + (l >> 2);
            float s0 = 0.f, s1 = 0.f;
#pragma unroll
            for (int nt = 0; nt < 8; nt++) {
                int col = n0 + wn * 64 + nt * 8 + (l & 3) * 2;
                float b0 = bias[col], b1 = bias[col + 1];
                float w0 = wp2[col],  w1 = wp2[col + 1];
                s0 += fmaxf(acc[mt][nt][0] + b0, 0.f) * w0
                    + fmaxf(acc[mt][nt][1] + b1, 0.f) * w1;
                s1 += fmaxf(acc[mt][nt][2] + b0, 0.f) * w0
                    + fmaxf(acc[mt][nt][3] + b1, 0.f) * w1;
            }
            atomicAdd(&g_lacc[row0 + rloc], s0);
            atomicAdd(&g_lacc[row0 + rloc + 8], s1);
        }
    } else {
#pragma unroll
        for (int mt = 0; mt < 2; mt++) {
            int r0 = row0 + wm * 32 + mt * 16 + (l >> 2);
#pragma unroll
            for (int nt = 0; nt < 8; nt++) {
                int col = n0 + wn * 64 + nt * 8 + (l & 3) * 2;
                float b0 = bias[col], b1 = bias[col + 1];
                float v0 = acc[mt][nt][0] + b0, v1 = acc[mt][nt][1] + b1;
                float v2 = acc[mt][nt][2] + b0, v3 = acc[mt][nt][3] + b1;
                if (MODE == 1) {
                    v0 = fmaxf(v0, 0.f); v1 = fmaxf(v1, 0.f);
                    v2 = fmaxf(v2, 0.f); v3 = fmaxf(v3, 0.f);
                }
                if (r0 < NN)
                    *(float2*)(outp + (size_t)r0 * HIDD + col) = make_float2(v0, v1);
                if (r0 + 8 < NN)
                    *(float2*)(outp + (size_t)(r0 + 8) * HIDD + col) = make_float2(v2, v3);
            }
        }
    }
}

// ---------------- launcher ------------------------------------------------------
extern "C" void kernel_launch(void* const* d_in, const int* in_sizes, int n_in,
                              void* d_out, int out_size) {
    (void)in_sizes; (void)n_in; (void)out_size;
    const float* x     = (const float*)d_in[0];
    const void*  ei    = d_in[1];
    const void*  sidx  = d_in[3];
    const void*  didx  = d_in[4];
    const float* w_emb = (const float*)d_in[5];
    const float* b_emb = (const float*)d_in[6];
    const float* wl0 = (const float*)d_in[8];
    const float* bl0 = (const float*)d_in[9];
    const float* wr0 = (const float*)d_in[10];
    const float* wl1 = (const float*)d_in[13];
    const float* bl1 = (const float*)d_in[14];
    const float* wr1 = (const float*)d_in[15];
    const float* wp1 = (const float*)d_in[18];
    const float* bp1 = (const float*)d_in[19];
    const float* wp2 = (const float*)d_in[20];
    const float* bp2 = (const float*)d_in[21];
    float* out = (float*)d_out;

    cudaFuncSetAttribute(gemm_tc<0>, cudaFuncAttributeMaxDynamicSharedMemorySize, SMEMB);
    cudaFuncSetAttribute(gemm_tc<1>, cudaFuncAttributeMaxDynamicSharedMemorySize, SMEMB);
    cudaFuncSetAttribute(gemm_tc<2>, cudaFuncAttributeMaxDynamicSharedMemorySize, SMEMB);

    __half *wembC, *wl0C, *wr0C, *wl1C, *wr1C, *wp1C;
    float *hbuf, *aggbuf, *h2buf, *combbuf;
    cudaGetSymbolAddress((void**)&wembC, g_wembC);
    cudaGetSymbolAddress((void**)&wl0C, g_wl0C);
    cudaGetSymbolAddress((void**)&wr0C, g_wr0C);
    cudaGetSymbolAddress((void**)&wl1C, g_wl1C);
    cudaGetSymbolAddress((void**)&wr1C, g_wr1C);
    cudaGetSymbolAddress((void**)&wp1C, g_wp1C);
    cudaGetSymbolAddress((void**)&hbuf, g_h);
    cudaGetSymbolAddress((void**)&aggbuf, g_agg);
    cudaGetSymbolAddress((void**)&h2buf, g_h2);
    cudaGetSymbolAddress((void**)&combbuf, g_comb);

    const int zgrid = (NN * HIDD + 255) / 256;
    dim3 ggrid((NN + 127) / 128, 2);         // 782 x 2
    dim3 lgrid(NL / 128, 2);                 // 128 x 2

    // launch order chosen so ncu (-s 5 -c 1) captures the first sage gemm
    prep_kernel<<<(557056 + 255) / 256, 256>>>(ei, w_emb, wl0, wr0, wl1, wr1, wp1); // 0
    zero_kernel<<<zgrid, 256>>>(1);                                                 // 1
    deg_kernel<<<(NE + 255) / 256, 256>>>(ei);                                      // 2
    gemm_tc<0><<<ggrid, 256, SMEMB>>>(x, nullptr, wembC, nullptr,
                                      b_emb, nullptr, hbuf);                        // 3
    agg_kernel<<<NE / 4, 256>>>(hbuf, ei);                                          // 4
    gemm_tc<1><<<ggrid, 256, SMEMB>>>(hbuf, aggbuf, wl0C, wr0C,
                                      bl0, nullptr, h2buf);                         // 5 <- ncu
    zero_kernel<<<zgrid, 256>>>(0);                                                 // 6
    agg_kernel<<<NE / 4, 256>>>(h2buf, ei);                                         // 7
    gemm_tc<1><<<ggrid, 256, SMEMB>>>(h2buf, aggbuf, wl1C, wr1C,
                                      bl1, nullptr, hbuf);                          // 8
    comb_kernel<<<NL * 64 / 256, 256>>>(hbuf, sidx, didx);                          // 9
    gemm_tc<2><<<lgrid, 256, SMEMB>>>(combbuf, nullptr, wp1C, nullptr,
                                      bp1, wp2, nullptr);                           // 10
    linkfin_kernel<<<NL / 256, 256>>>(bp2, out);                                    // 11
}

// round 10
// speedup vs baseline: 14.6016x; 1.2302x over previous
#include <cuda_runtime.h>
#include <cuda_fp16.h>
#include <math.h>
#include <stdint.h>

#define NN   100000
#define NE   500000
#define FEATD 128
#define HIDD  256
#define NL   16384

// ---------------- persistent scratch ------------------------------------------
__device__ float g_deg[NN];
__device__ float g_h  [(size_t)NN * HIDD];
__device__ float g_agg[(size_t)NN * HIDD];
__device__ float g_h2 [(size_t)NN * HIDD];
__device__ float g_comb[(size_t)NL * 4 * HIDD];
__device__ float g_lacc[NL];
__device__ int   g_is64;

// fp16 weights (plain, not split — A is the split operand)
__device__ __half g_wembC[HIDD*FEATD];
__device__ __half g_wl0C[HIDD*HIDD];
__device__ __half g_wr0C[HIDD*HIDD];
__device__ __half g_wl1C[HIDD*HIDD];
__device__ __half g_wr1C[HIDD*HIDD];
__device__ __half g_wp1C[HIDD*4*HIDD];

// ---------------- helpers -------------------------------------------------------
__device__ __forceinline__ uint32_t smem_u32(const void* p) {
    uint32_t a;
    asm("{ .reg .u64 t; cvta.to.shared.u64 t, %1; cvt.u32.u64 %0, t; }"
        : "=r"(a) : "l"(p));
    return a;
}
static __device__ __forceinline__ uint32_t swz(uint32_t x) {
    return x ^ ((x >> 3) & 0x70);
}
// fp16 split: v = hi + lo (each fp16), packed as f16x2 words
__device__ __forceinline__ void split2h(float a, float b, uint32_t& hi, uint32_t& lo) {
    __half ha = __float2half(a), hb = __float2half(b);
    __half la = __float2half(a - __half2float(ha));
    __half lb = __float2half(b - __half2float(hb));
    hi = ((uint32_t)__half_as_ushort(hb) << 16) | __half_as_ushort(ha);
    lo = ((uint32_t)__half_as_ushort(lb) << 16) | __half_as_ushort(la);
}
__device__ __forceinline__ long long idx_at(const void* p, long long i, int is64) {
    if (is64) return ((const long long*)p)[i];
    return (long long)((const int*)p)[i];
}
__device__ __forceinline__ void ldmx4(uint32_t* r, uint32_t a) {
    asm volatile("ldmatrix.sync.aligned.m8n8.x4.shared.b16 {%0,%1,%2,%3}, [%4];"
                 : "=r"(r[0]), "=r"(r[1]), "=r"(r[2]), "=r"(r[3]) : "r"(a));
}
#define MMA_F16(d, a, b) \
    asm volatile("mma.sync.aligned.m16n8k16.row.col.f32.f16.f16.f32 " \
        "{%0,%1,%2,%3}, {%4,%5,%6,%7}, {%8,%9}, {%0,%1,%2,%3};" \
        : "+f"((d)[0]), "+f"((d)[1]), "+f"((d)[2]), "+f"((d)[3]) \
        : "r"((a)[0]), "r"((a)[1]), "r"((a)[2]), "r"((a)[3]), \
          "r"((b)[0]), "r"((b)[1]))

// ---------------- prep: detect + all weight conversions (1 launch) --------------
__global__ void prep_kernel(const void* ei,
                            const float* __restrict__ wemb,
                            const float* __restrict__ wl0, const float* __restrict__ wr0,
                            const float* __restrict__ wl1, const float* __restrict__ wr1,
                            const float* __restrict__ wp1) {
    int i = blockIdx.x * 256 + threadIdx.x;
    if (i == 0) {
        const unsigned* w = (const unsigned*)ei;
        int zeros = 0;
        for (int j = 1; j < 128; j += 2) zeros += (w[j] == 0u);
        g_is64 = (zeros >= 50) ? 1 : 0;
    }
    if (i < 32768)       g_wembC[i]          = __float2half(wemb[i]);
    else if (i < 98304)  g_wl0C[i - 32768]   = __float2half(wl0[i - 32768]);
    else if (i < 163840) g_wr0C[i - 98304]   = __float2half(wr0[i - 98304]);
    else if (i < 229376) g_wl1C[i - 163840]  = __float2half(wl1[i - 163840]);
    else if (i < 294912) g_wr1C[i - 229376]  = __float2half(wr1[i - 229376]);
    else if (i < 557056) g_wp1C[i - 294912]  = __float2half(wp1[i - 294912]);
}

// ---------------- misc small kernels -------------------------------------------
__global__ void zero_kernel(int with_deg) {
    long long i = (long long)blockIdx.x * blockDim.x + threadIdx.x;
    if (i < (long long)NN * HIDD / 4)
        ((float4*)g_agg)[i] = make_float4(0.f, 0.f, 0.f, 0.f);
    if (with_deg && i < NN) g_deg[i]  = 0.f;
    if (with_deg && i < NL) g_lacc[i] = 0.f;
}

__global__ void deg_kernel(const void* ei) {
    int e = blockIdx.x * blockDim.x + threadIdx.x;
    if (e < NE) {
        long long d = idx_at(ei, (long long)NE + e, g_is64);
        atomicAdd(&g_deg[d], 1.f);
    }
}

__global__ __launch_bounds__(256) void agg_kernel(const float* __restrict__ h,
                                                  const void* ei) {
    int e = blockIdx.x * 4 + (threadIdx.x >> 6);
    if (e >= NE) return;
    int lane = threadIdx.x & 63;
    int is64 = g_is64;
    long long s = idx_at(ei, e, is64);
    long long d = idx_at(ei, (long long)NE + e, is64);
    const float4 v = *(const float4*)(h + (size_t)s * HIDD + lane * 4);
    float* dp = g_agg + (size_t)d * HIDD + lane * 4;
    asm volatile("red.global.add.v4.f32 [%0], {%1,%2,%3,%4};"
                 :: "l"(dp), "f"(v.x), "f"(v.y), "f"(v.z), "f"(v.w) : "memory");
}

__global__ __launch_bounds__(256) void comb_kernel(const float* __restrict__ h,
                                                   const void* sp, const void* dp) {
    int t = blockIdx.x * 256 + threadIdx.x;   // NL*64 total
    int l = t >> 6, q = t & 63;
    int is64 = g_is64;
    long long si = idx_at(sp, l, is64);
    long long di = idx_at(dp, l, is64);
    float4 s4 = *(const float4*)(h + (size_t)si * HIDD + q * 4);
    float4 d4 = *(const float4*)(h + (size_t)di * HIDD + q * 4);
    float* row = g_comb + (size_t)l * 1024;
    *(float4*)(row + q * 4)       = s4;
    *(float4*)(row + 256 + q * 4) = d4;
    *(float4*)(row + 512 + q * 4) = make_float4(s4.x*d4.x, s4.y*d4.y, s4.z*d4.z, s4.w*d4.w);
    *(float4*)(row + 768 + q * 4) = make_float4(fabsf(s4.x-d4.x), fabsf(s4.y-d4.y),
                                                fabsf(s4.z-d4.z), fabsf(s4.w-d4.w));
}

__global__ void linkfin_kernel(const float* __restrict__ bp2, float* __restrict__ out) {
    int i = blockIdx.x * 256 + threadIdx.x;
    if (i < NL) out[i] = 1.f / (1.f + expf(-(g_lacc[i] + bp2[0])));
}

// ---------------- mma.sync split-fp16 GEMM --------------------------------------
// D[128,128-slice] = A[128,K] @ W[256,K]^T,  2 products: Ah*W + Al*W (W plain fp16)
// MODE 0: embed (K=128, out = D + bias)
// MODE 1: sage  (K=2x256: mean@wl^T + h@wr^T; out = relu(D + bias))
// MODE 2: link  (K=1024; epilogue: atomicAdd(relu(D+bp1).wp2) per row)
// Producer loops use linear (fully coalesced) lane->address maps.
// NOTE: A-tile smem slot is 8 bytes per float4 (4 fp16), hence `c4 * 8`.

#define SA_H   0
#define SA_L   16384
#define SW_    32768
#define S_MISC 49152
#define SMEMB  (S_MISC + 512 + 1024)

template <int MODE>
__global__ __launch_bounds__(256, 2) void gemm_tc(
    const float* __restrict__ A, const float* __restrict__ Aagg,
    const __half* __restrict__ W1, const __half* __restrict__ W2,
    const float* __restrict__ bias, const float* __restrict__ wp2,
    float* __restrict__ outp)
{
    extern __shared__ char smraw[];
    char* smc = (char*)(((uintptr_t)smraw + 1023) & ~(uintptr_t)1023);
    const uint32_t sbase = smem_u32(smc);
    const int tid = threadIdx.x;
    const int wid = tid >> 5, l = tid & 31;
    const int wm = wid >> 1, wn = wid & 1;       // 4 x 2 warp grid
    const int row0 = blockIdx.x * 128;
    const int n0   = blockIdx.y * 128;

    constexpr int NCH = (MODE == 0) ? 2 : (MODE == 1) ? 8 : 16;
    constexpr int KA  = (MODE == 0) ? FEATD : (MODE == 1) ? HIDD : 1024;

    float* invd_s = (float*)(smc + S_MISC);
    if (MODE == 1 && tid < 128) {
        int row = row0 + tid;
        invd_s[tid] = (row < NN) ? 1.f / (g_deg[row] + 1.f) : 0.f;
    }
    if (MODE == 1) __syncthreads();

    float acc[2][8][4];
#pragma unroll
    for (int mt = 0; mt < 2; mt++)
#pragma unroll
        for (int nt = 0; nt < 8; nt++)
#pragma unroll
            for (int j = 0; j < 4; j++) acc[mt][nt][j] = 0.f;

    for (int c = 0; c < NCH; c++) {
        const int colbase = (MODE == 1) ? ((c & 3) * 64) : (c * 64);

        // ---- A tile: 128 x 64 fp32 -> fp16 hi/lo, swizzled; coalesced map ----
#pragma unroll
        for (int i = 0; i < 8; i++) {
            const int id = i * 256 + tid;     // 2048 float4 slots
            const int r  = id >> 4;           // tile row 0..127 (2 rows / warp)
            const int c4 = id & 15;           // float4 index within 64-col row
            float4 v = make_float4(0.f, 0.f, 0.f, 0.f);
            const bool rv = (MODE == 2) || (row0 + r < NN);
            if (rv) {
                const size_t abase = (size_t)(row0 + r) * KA + colbase + c4 * 4;
                if (MODE == 1) {
                    float4 hv = *(const float4*)(A + abase);
                    if (c < 4) {
                        float4 av = *(const float4*)(Aagg + abase);
                        float iv = invd_s[r];
                        v = make_float4((av.x + hv.x) * iv, (av.y + hv.y) * iv,
                                        (av.z + hv.z) * iv, (av.w + hv.w) * iv);
                    } else v = hv;
                } else {
                    v = *(const float4*)(A + abase);
                }
            }
            uint32_t h0, l0, h1, l1;
            split2h(v.x, v.y, h0, l0);
            split2h(v.z, v.w, h1, l1);
            uint32_t s = swz(r * 128 + c4 * 8);   // 4 fp16 = 8 bytes per slot
            *(uint2*)(smc + SA_H + s) = make_uint2(h0, h1);
            *(uint2*)(smc + SA_L + s) = make_uint2(l0, l1);
        }
        // ---- W tile: 128 x 64 fp16, swizzled; coalesced map ----
        {
            const __half* W = (MODE == 1 && c >= 4) ? W2 : W1;
#pragma unroll
            for (int j = 0; j < 4; j++) {
                const int id  = j * 256 + tid;   // 1024 uint4 slots
                const int r   = id >> 3;         // tile row 0..127 (4 rows / warp)
                const int c16 = id & 7;          // uint4 index within 128B row
                uint4 hv = *(const uint4*)(W + (size_t)(n0 + r) * KA + colbase + c16 * 8);
                *(uint4*)(smc + SW_ + swz(r * 128 + c16 * 16)) = hv;
            }
        }
        __syncthreads();

        // ---- mma phase: 2 products over this K=64 chunk ----
#pragma unroll
        for (int kk = 0; kk < 4; kk++) {
            const uint32_t kbyte = kk * 32;
            uint32_t ah[2][4], al[2][4];
#pragma unroll
            for (int mt = 0; mt < 2; mt++) {
                uint32_t off = swz((wm * 32 + mt * 16 + (l & 15)) * 128 +
                                   kbyte + ((l >> 4) << 4));
                ldmx4(ah[mt], sbase + SA_H + off);
                ldmx4(al[mt], sbase + SA_L + off);
            }
            uint32_t bf[8][2];
#pragma unroll
            for (int ntb = 0; ntb < 4; ntb++) {
                const int nt2 = ntb * 2;
                uint32_t off = swz((wn * 64 + (nt2 + ((l >> 4) & 1)) * 8 + (l & 7)) * 128
                                   + kbyte + (((l >> 3) & 1) << 4));
                uint32_t r[4];
                ldmx4(r, sbase + SW_ + off);
                bf[nt2][0] = r[0]; bf[nt2][1] = r[1];
                bf[nt2 + 1][0] = r[2]; bf[nt2 + 1][1] = r[3];
            }
#pragma unroll
            for (int nt = 0; nt < 8; nt++)
#pragma unroll
                for (int mt = 0; mt < 2; mt++) {
                    MMA_F16(acc[mt][nt], ah[mt], bf[nt]);
                    MMA_F16(acc[mt][nt], al[mt], bf[nt]);
                }
        }
        __syncthreads();
    }

    // ---- epilogue ----
    if (MODE == 2) {
#pragma unroll
        for (int mt = 0; mt < 2; mt++) {
            int rloc = wm * 32 + mt * 16 + (l >> 2);
            float s0 = 0.f, s1 = 0.f;
#pragma unroll
            for (int nt = 0; nt < 8; nt++) {
                int col = n0 + wn * 64 + nt * 8 + (l & 3) * 2;
                float b0 = bias[col], b1 = bias[col + 1];
                float w0 = wp2[col],  w1 = wp2[col + 1];
                s0 += fmaxf(acc[mt][nt][0] + b0, 0.f) * w0
                    + fmaxf(acc[mt][nt][1] + b1, 0.f) * w1;
                s1 += fmaxf(acc[mt][nt][2] + b0, 0.f) * w0
                    + fmaxf(acc[mt][nt][3] + b1, 0.f) * w1;
            }
            atomicAdd(&g_lacc[row0 + rloc], s0);
            atomicAdd(&g_lacc[row0 + rloc + 8], s1);
        }
    } else {
#pragma unroll
        for (int mt = 0; mt < 2; mt++) {
            int r0 = row0 + wm * 32 + mt * 16 + (l >> 2);
#pragma unroll
            for (int nt = 0; nt < 8; nt++) {
                int col = n0 + wn * 64 + nt * 8 + (l & 3) * 2;
                float b0 = bias[col], b1 = bias[col + 1];
                float v0 = acc[mt][nt][0] + b0, v1 = acc[mt][nt][1] + b1;
                float v2 = acc[mt][nt][2] + b0, v3 = acc[mt][nt][3] + b1;
                if (MODE == 1) {
                    v0 = fmaxf(v0, 0.f); v1 = fmaxf(v1, 0.f);
                    v2 = fmaxf(v2, 0.f); v3 = fmaxf(v3, 0.f);
                }
                if (r0 < NN)
                    *(float2*)(outp + (size_t)r0 * HIDD + col) = make_float2(v0, v1);
                if (r0 + 8 < NN)
                    *(float2*)(outp + (size_t)(r0 + 8) * HIDD + col) = make_float2(v2, v3);
            }
        }
    }
}

// ---------------- launcher ------------------------------------------------------
extern "C" void kernel_launch(void* const* d_in, const int* in_sizes, int n_in,
                              void* d_out, int out_size) {
    (void)in_sizes; (void)n_in; (void)out_size;
    const float* x     = (const float*)d_in[0];
    const void*  ei    = d_in[1];
    const void*  sidx  = d_in[3];
    const void*  didx  = d_in[4];
    const float* w_emb = (const float*)d_in[5];
    const float* b_emb = (const float*)d_in[6];
    const float* wl0 = (const float*)d_in[8];
    const float* bl0 = (const float*)d_in[9];
    const float* wr0 = (const float*)d_in[10];
    const float* wl1 = (const float*)d_in[13];
    const float* bl1 = (const float*)d_in[14];
    const float* wr1 = (const float*)d_in[15];
    const float* wp1 = (const float*)d_in[18];
    const float* bp1 = (const float*)d_in[19];
    const float* wp2 = (const float*)d_in[20];
    const float* bp2 = (const float*)d_in[21];
    float* out = (float*)d_out;

    cudaFuncSetAttribute(gemm_tc<0>, cudaFuncAttributeMaxDynamicSharedMemorySize, SMEMB);
    cudaFuncSetAttribute(gemm_tc<1>, cudaFuncAttributeMaxDynamicSharedMemorySize, SMEMB);
    cudaFuncSetAttribute(gemm_tc<2>, cudaFuncAttributeMaxDynamicSharedMemorySize, SMEMB);

    __half *wembC, *wl0C, *wr0C, *wl1C, *wr1C, *wp1C;
    float *hbuf, *aggbuf, *h2buf, *combbuf;
    cudaGetSymbolAddress((void**)&wembC, g_wembC);
    cudaGetSymbolAddress((void**)&wl0C, g_wl0C);
    cudaGetSymbolAddress((void**)&wr0C, g_wr0C);
    cudaGetSymbolAddress((void**)&wl1C, g_wl1C);
    cudaGetSymbolAddress((void**)&wr1C, g_wr1C);
    cudaGetSymbolAddress((void**)&wp1C, g_wp1C);
    cudaGetSymbolAddress((void**)&hbuf, g_h);
    cudaGetSymbolAddress((void**)&aggbuf, g_agg);
    cudaGetSymbolAddress((void**)&h2buf, g_h2);
    cudaGetSymbolAddress((void**)&combbuf, g_comb);

    const int zgrid = (NN * HIDD / 4 + 255) / 256;
    dim3 ggrid((NN + 127) / 128, 2);         // 782 x 2
    dim3 lgrid(NL / 128, 2);                 // 128 x 2

    // launch order chosen so ncu (-s 5 -c 1) captures the first sage gemm
    prep_kernel<<<(557056 + 255) / 256, 256>>>(ei, w_emb, wl0, wr0, wl1, wr1, wp1); // 0
    zero_kernel<<<zgrid, 256>>>(1);                                                 // 1
    deg_kernel<<<(NE + 255) / 256, 256>>>(ei);                                      // 2
    gemm_tc<0><<<ggrid, 256, SMEMB>>>(x, nullptr, wembC, nullptr,
                                      b_emb, nullptr, hbuf);                        // 3
    agg_kernel<<<NE / 4, 256>>>(hbuf, ei);                                          // 4
    gemm_tc<1><<<ggrid, 256, SMEMB>>>(hbuf, aggbuf, wl0C, wr0C,
                                      bl0, nullptr, h2buf);                         // 5 <- ncu
    zero_kernel<<<zgrid, 256>>>(0);                                                 // 6
    agg_kernel<<<NE / 4, 256>>>(h2buf, ei);                                         // 7
    gemm_tc<1><<<ggrid, 256, SMEMB>>>(h2buf, aggbuf, wl1C, wr1C,
                                      bl1, nullptr, hbuf);                          // 8
    comb_kernel<<<NL * 64 / 256, 256>>>(hbuf, sidx, didx);                          // 9
    gemm_tc<2><<<lgrid, 256, SMEMB>>>(combbuf, nullptr, wp1C, nullptr,
                                      bp1, wp2, nullptr);                           // 10
    linkfin_kernel<<<NL / 256, 256>>>(bp2, out);                                    // 11
}

// round 12
// speedup vs baseline: 15.5102x; 1.0622x over previous
// R12: resubmission of the BN=256 kernel — R11 failed with "device busy or
// unavailable" at harness context creation (infra, not kernel). Source is
// functionally identical to R11.
#include <cuda_runtime.h>
#include <cuda_fp16.h>
#include <math.h>
#include <stdint.h>

#define NN   100000
#define NE   500000
#define FEATD 128
#define HIDD  256
#define NL   16384

// ---------------- persistent scratch ------------------------------------------
__device__ float g_deg[NN];
__device__ float g_h  [(size_t)NN * HIDD];
__device__ float g_agg[(size_t)NN * HIDD];
__device__ float g_h2 [(size_t)NN * HIDD];
__device__ float g_comb[(size_t)NL * 4 * HIDD];
__device__ float g_lacc[NL];
__device__ int   g_is64;

// fp16 weights (plain, not split — A is the split operand)
__device__ __half g_wembC[HIDD*FEATD];
__device__ __half g_wl0C[HIDD*HIDD];
__device__ __half g_wr0C[HIDD*HIDD];
__device__ __half g_wl1C[HIDD*HIDD];
__device__ __half g_wr1C[HIDD*HIDD];
__device__ __half g_wp1C[HIDD*4*HIDD];

// ---------------- helpers -------------------------------------------------------
__device__ __forceinline__ uint32_t smem_u32(const void* p) {
    uint32_t a;
    asm("{ .reg .u64 t; cvta.to.shared.u64 t, %1; cvt.u32.u64 %0, t; }"
        : "=r"(a) : "l"(p));
    return a;
}
static __device__ __forceinline__ uint32_t swz(uint32_t x) {
    return x ^ ((x >> 3) & 0x70);
}
// fp16 split: v = hi + lo (each fp16), packed as f16x2 words
__device__ __forceinline__ void split2h(float a, float b, uint32_t& hi, uint32_t& lo) {
    __half ha = __float2half(a), hb = __float2half(b);
    __half la = __float2half(a - __half2float(ha));
    __half lb = __float2half(b - __half2float(hb));
    hi = ((uint32_t)__half_as_ushort(hb) << 16) | __half_as_ushort(ha);
    lo = ((uint32_t)__half_as_ushort(lb) << 16) | __half_as_ushort(la);
}
__device__ __forceinline__ long long idx_at(const void* p, long long i, int is64) {
    if (is64) return ((const long long*)p)[i];
    return (long long)((const int*)p)[i];
}
__device__ __forceinline__ void ldmx4(uint32_t* r, uint32_t a) {
    asm volatile("ldmatrix.sync.aligned.m8n8.x4.shared.b16 {%0,%1,%2,%3}, [%4];"
                 : "=r"(r[0]), "=r"(r[1]), "=r"(r[2]), "=r"(r[3]) : "r"(a));
}
#define MMA_F16(d, a, b) \
    asm volatile("mma.sync.aligned.m16n8k16.row.col.f32.f16.f16.f32 " \
        "{%0,%1,%2,%3}, {%4,%5,%6,%7}, {%8,%9}, {%0,%1,%2,%3};" \
        : "+f"((d)[0]), "+f"((d)[1]), "+f"((d)[2]), "+f"((d)[3]) \
        : "r"((a)[0]), "r"((a)[1]), "r"((a)[2]), "r"((a)[3]), \
          "r"((b)[0]), "r"((b)[1]))

// ---------------- prep: detect + all weight conversions (1 launch) --------------
__global__ void prep_kernel(const void* ei,
                            const float* __restrict__ wemb,
                            const float* __restrict__ wl0, const float* __restrict__ wr0,
                            const float* __restrict__ wl1, const float* __restrict__ wr1,
                            const float* __restrict__ wp1) {
    int i = blockIdx.x * 256 + threadIdx.x;
    if (i == 0) {
        const unsigned* w = (const unsigned*)ei;
        int zeros = 0;
        for (int j = 1; j < 128; j += 2) zeros += (w[j] == 0u);
        g_is64 = (zeros >= 50) ? 1 : 0;
    }
    if (i < 32768)       g_wembC[i]          = __float2half(wemb[i]);
    else if (i < 98304)  g_wl0C[i - 32768]   = __float2half(wl0[i - 32768]);
    else if (i < 163840) g_wr0C[i - 98304]   = __float2half(wr0[i - 98304]);
    else if (i < 229376) g_wl1C[i - 163840]  = __float2half(wl1[i - 163840]);
    else if (i < 294912) g_wr1C[i - 229376]  = __float2half(wr1[i - 229376]);
    else if (i < 557056) g_wp1C[i - 294912]  = __float2half(wp1[i - 294912]);
}

// ---------------- misc small kernels -------------------------------------------
__global__ void zero_kernel(int with_deg) {
    long long i = (long long)blockIdx.x * blockDim.x + threadIdx.x;
    if (i < (long long)NN * HIDD / 4)
        ((float4*)g_agg)[i] = make_float4(0.f, 0.f, 0.f, 0.f);
    if (with_deg && i < NN) g_deg[i]  = 0.f;
    if (with_deg && i < NL) g_lacc[i] = 0.f;
}

__global__ void deg_kernel(const void* ei) {
    int e = blockIdx.x * blockDim.x + threadIdx.x;
    if (e < NE) {
        long long d = idx_at(ei, (long long)NE + e, g_is64);
        atomicAdd(&g_deg[d], 1.f);
    }
}

__global__ __launch_bounds__(256) void agg_kernel(const float* __restrict__ h,
                                                  const void* ei) {
    int e = blockIdx.x * 4 + (threadIdx.x >> 6);
    if (e >= NE) return;
    int lane = threadIdx.x & 63;
    int is64 = g_is64;
    long long s = idx_at(ei, e, is64);
    long long d = idx_at(ei, (long long)NE + e, is64);
    const float4 v = *(const float4*)(h + (size_t)s * HIDD + lane * 4);
    float* dp = g_agg + (size_t)d * HIDD + lane * 4;
    asm volatile("red.global.add.v4.f32 [%0], {%1,%2,%3,%4};"
                 :: "l"(dp), "f"(v.x), "f"(v.y), "f"(v.z), "f"(v.w) : "memory");
}

__global__ __launch_bounds__(256) void comb_kernel(const float* __restrict__ h,
                                                   const void* sp, const void* dp) {
    int t = blockIdx.x * 256 + threadIdx.x;   // NL*64 total
    int l = t >> 6, q = t & 63;
    int is64 = g_is64;
    long long si = idx_at(sp, l, is64);
    long long di = idx_at(dp, l, is64);
    float4 s4 = *(const float4*)(h + (size_t)si * HIDD + q * 4);
    float4 d4 = *(const float4*)(h + (size_t)di * HIDD + q * 4);
    float* row = g_comb + (size_t)l * 1024;
    *(float4*)(row + q * 4)       = s4;
    *(float4*)(row + 256 + q * 4) = d4;
    *(float4*)(row + 512 + q * 4) = make_float4(s4.x*d4.x, s4.y*d4.y, s4.z*d4.z, s4.w*d4.w);
    *(float4*)(row + 768 + q * 4) = make_float4(fabsf(s4.x-d4.x), fabsf(s4.y-d4.y),
                                                fabsf(s4.z-d4.z), fabsf(s4.w-d4.w));
}

__global__ void linkfin_kernel(const float* __restrict__ bp2, float* __restrict__ out) {
    int i = blockIdx.x * 256 + threadIdx.x;
    if (i < NL) out[i] = 1.f / (1.f + expf(-(g_lacc[i] + bp2[0])));
}

// ---------------- mma.sync split-fp16 GEMM, BN=256 (A read ONCE) ----------------
// D[128, 256] = A[128,K] @ W[256,K]^T,  2 products: Ah*W + Al*W (W plain fp16)
// 512 threads, 4x4 warp grid, 32x64 warp tiles.
// MODE 0: embed (K=128, out = D + bias)
// MODE 1: sage  (K=2x256: mean@wl^T + h@wr^T; out = relu(D + bias))
// MODE 2: link  (K=1024; epilogue: atomicAdd(relu(D+bp1).wp2) per row)

#define SA_H   0
#define SA_L   16384
#define SW_    32768          // 256 rows x 128B = 32KB
#define S_MISC 65536
#define SMEMB  (S_MISC + 512 + 1024)

template <int MODE>
__global__ __launch_bounds__(512, 1) void gemm_tc(
    const float* __restrict__ A, const float* __restrict__ Aagg,
    const __half* __restrict__ W1, const __half* __restrict__ W2,
    const float* __restrict__ bias, const float* __restrict__ wp2,
    float* __restrict__ outp)
{
    extern __shared__ char smraw[];
    char* smc = (char*)(((uintptr_t)smraw + 1023) & ~(uintptr_t)1023);
    const uint32_t sbase = smem_u32(smc);
    const int tid = threadIdx.x;
    const int wid = tid >> 5, l = tid & 31;
    const int wm = wid >> 2, wn = wid & 3;       // 4 x 4 warp grid
    const int row0 = blockIdx.x * 128;

    constexpr int NCH = (MODE == 0) ? 2 : (MODE == 1) ? 8 : 16;
    constexpr int KA  = (MODE == 0) ? FEATD : (MODE == 1) ? HIDD : 1024;

    float* invd_s = (float*)(smc + S_MISC);
    if (MODE == 1 && tid < 128) {
        int row = row0 + tid;
        invd_s[tid] = (row < NN) ? 1.f / (g_deg[row] + 1.f) : 0.f;
    }
    if (MODE == 1) __syncthreads();

    float acc[2][8][4];
#pragma unroll
    for (int mt = 0; mt < 2; mt++)
#pragma unroll
        for (int nt = 0; nt < 8; nt++)
#pragma unroll
            for (int j = 0; j < 4; j++) acc[mt][nt][j] = 0.f;

    for (int c = 0; c < NCH; c++) {
        const int colbase = (MODE == 1) ? ((c & 3) * 64) : (c * 64);

        // ---- A tile: 128 x 64 fp32 -> fp16 hi/lo, swizzled; coalesced map ----
#pragma unroll
        for (int i = 0; i < 4; i++) {
            const int id = i * 512 + tid;     // 2048 float4 slots
            const int r  = id >> 4;           // tile row 0..127
            const int c4 = id & 15;           // float4 index within 64-col row
            float4 v = make_float4(0.f, 0.f, 0.f, 0.f);
            const bool rv = (MODE == 2) || (row0 + r < NN);
            if (rv) {
                const size_t abase = (size_t)(row0 + r) * KA + colbase + c4 * 4;
                if (MODE == 1) {
                    float4 hv = *(const float4*)(A + abase);
                    if (c < 4) {
                        float4 av = *(const float4*)(Aagg + abase);
                        float iv = invd_s[r];
                        v = make_float4((av.x + hv.x) * iv, (av.y + hv.y) * iv,
                                        (av.z + hv.z) * iv, (av.w + hv.w) * iv);
                    } else v = hv;
                } else {
                    v = *(const float4*)(A + abase);
                }
            }
            uint32_t h0, l0, h1, l1;
            split2h(v.x, v.y, h0, l0);
            split2h(v.z, v.w, h1, l1);
            uint32_t s = swz(r * 128 + c4 * 8);   // 4 fp16 = 8 bytes per slot
            *(uint2*)(smc + SA_H + s) = make_uint2(h0, h1);
            *(uint2*)(smc + SA_L + s) = make_uint2(l0, l1);
        }
        // ---- W tile: 256 x 64 fp16, swizzled; coalesced map ----
        {
            const __half* W = (MODE == 1 && c >= 4) ? W2 : W1;
#pragma unroll
            for (int j = 0; j < 4; j++) {
                const int id  = j * 512 + tid;   // 2048 uint4 slots
                const int r   = id >> 3;         // tile row 0..255
                const int c16 = id & 7;          // uint4 index within 128B row
                uint4 hv = *(const uint4*)(W + (size_t)r * KA + colbase + c16 * 8);
                *(uint4*)(smc + SW_ + swz(r * 128 + c16 * 16)) = hv;
            }
        }
        __syncthreads();

        // ---- mma phase: 2 products over this K=64 chunk ----
#pragma unroll
        for (int kk = 0; kk < 4; kk++) {
            const uint32_t kbyte = kk * 32;
            uint32_t ah[2][4], al[2][4];
#pragma unroll
            for (int mt = 0; mt < 2; mt++) {
                uint32_t off = swz((wm * 32 + mt * 16 + (l & 15)) * 128 +
                                   kbyte + ((l >> 4) << 4));
                ldmx4(ah[mt], sbase + SA_H + off);
                ldmx4(al[mt], sbase + SA_L + off);
            }
            uint32_t bf[8][2];
#pragma unroll
            for (int ntb = 0; ntb < 4; ntb++) {
                const int nt2 = ntb * 2;
                uint32_t off = swz((wn * 64 + (nt2 + ((l >> 4) & 1)) * 8 + (l & 7)) * 128
                                   + kbyte + (((l >> 3) & 1) << 4));
                uint32_t r[4];
                ldmx4(r, sbase + SW_ + off);
                bf[nt2][0] = r[0]; bf[nt2][1] = r[1];
                bf[nt2 + 1][0] = r[2]; bf[nt2 + 1][1] = r[3];
            }
#pragma unroll
            for (int nt = 0; nt < 8; nt++)
#pragma unroll
                for (int mt = 0; mt < 2; mt++) {
                    MMA_F16(acc[mt][nt], ah[mt], bf[nt]);
                    MMA_F16(acc[mt][nt], al[mt], bf[nt]);
                }
        }
        __syncthreads();
    }

    // ---- epilogue ----
    if (MODE == 2) {
#pragma unroll
        for (int mt = 0; mt < 2; mt++) {
            int rloc = wm * 32 + mt * 16 + (l >> 2);
            float s0 = 0.f, s1 = 0.f;
#pragma unroll
            for (int nt = 0; nt < 8; nt++) {
                int col = wn * 64 + nt * 8 + (l & 3) * 2;
                float b0 = bias[col], b1 = bias[col + 1];
                float w0 = wp2[col],  w1 = wp2[col + 1];
                s0 += fmaxf(acc[mt][nt][0] + b0, 0.f) * w0
                    + fmaxf(acc[mt][nt][1] + b1, 0.f) * w1;
                s1 += fmaxf(acc[mt][nt][2] + b0, 0.f) * w0
                    + fmaxf(acc[mt][nt][3] + b1, 0.f) * w1;
            }
            atomicAdd(&g_lacc[row0 + rloc], s0);
            atomicAdd(&g_lacc[row0 + rloc + 8], s1);
        }
    } else {
#pragma unroll
        for (int mt = 0; mt < 2; mt++) {
            int r0 = row0 + wm * 32 + mt * 16 + (l >> 2);
#pragma unroll
            for (int nt = 0; nt < 8; nt++) {
                int col = wn * 64 + nt * 8 + (l & 3) * 2;
                float b0 = bias[col], b1 = bias[col + 1];
                float v0 = acc[mt][nt][0] + b0, v1 = acc[mt][nt][1] + b1;
                float v2 = acc[mt][nt][2] + b0, v3 = acc[mt][nt][3] + b1;
                if (MODE == 1) {
                    v0 = fmaxf(v0, 0.f); v1 = fmaxf(v1, 0.f);
                    v2 = fmaxf(v2, 0.f); v3 = fmaxf(v3, 0.f);
                }
                if (r0 < NN)
                    *(float2*)(outp + (size_t)r0 * HIDD + col) = make_float2(v0, v1);
                if (r0 + 8 < NN)
                    *(float2*)(outp + (size_t)(r0 + 8) * HIDD + col) = make_float2(v2, v3);
            }
        }
    }
}

// ---------------- launcher ------------------------------------------------------
extern "C" void kernel_launch(void* const* d_in, const int* in_sizes, int n_in,
                              void* d_out, int out_size) {
    (void)in_sizes; (void)n_in; (void)out_size;
    const float* x     = (const float*)d_in[0];
    const void*  ei    = d_in[1];
    const void*  sidx  = d_in[3];
    const void*  didx  = d_in[4];
    const float* w_emb = (const float*)d_in[5];
    const float* b_emb = (const float*)d_in[6];
    const float* wl0 = (const float*)d_in[8];
    const float* bl0 = (const float*)d_in[9];
    const float* wr0 = (const float*)d_in[10];
    const float* wl1 = (const float*)d_in[13];
    const float* bl1 = (const float*)d_in[14];
    const float* wr1 = (const float*)d_in[15];
    const float* wp1 = (const float*)d_in[18];
    const float* bp1 = (const float*)d_in[19];
    const float* wp2 = (const float*)d_in[20];
    const float* bp2 = (const float*)d_in[21];
    float* out = (float*)d_out;

    cudaFuncSetAttribute(gemm_tc<0>, cudaFuncAttributeMaxDynamicSharedMemorySize, SMEMB);
    cudaFuncSetAttribute(gemm_tc<1>, cudaFuncAttributeMaxDynamicSharedMemorySize, SMEMB);
    cudaFuncSetAttribute(gemm_tc<2>, cudaFuncAttributeMaxDynamicSharedMemorySize, SMEMB);

    __half *wembC, *wl0C, *wr0C, *wl1C, *wr1C, *wp1C;
    float *hbuf, *aggbuf, *h2buf, *combbuf;
    cudaGetSymbolAddress((void**)&wembC, g_wembC);
    cudaGetSymbolAddress((void**)&wl0C, g_wl0C);
    cudaGetSymbolAddress((void**)&wr0C, g_wr0C);
    cudaGetSymbolAddress((void**)&wl1C, g_wl1C);
    cudaGetSymbolAddress((void**)&wr1C, g_wr1C);
    cudaGetSymbolAddress((void**)&wp1C, g_wp1C);
    cudaGetSymbolAddress((void**)&hbuf, g_h);
    cudaGetSymbolAddress((void**)&aggbuf, g_agg);
    cudaGetSymbolAddress((void**)&h2buf, g_h2);
    cudaGetSymbolAddress((void**)&combbuf, g_comb);

    const int zgrid = (NN * HIDD / 4 + 255) / 256;
    const int ggrid = (NN + 127) / 128;      // 782
    const int lgrid = NL / 128;              // 128

    // launch order chosen so ncu (-s 5 -c 1) captures the first sage gemm
    prep_kernel<<<(557056 + 255) / 256, 256>>>(ei, w_emb, wl0, wr0, wl1, wr1, wp1); // 0
    zero_kernel<<<zgrid, 256>>>(1);                                                 // 1
    deg_kernel<<<(NE + 255) / 256, 256>>>(ei);                                      // 2
    gemm_tc<0><<<ggrid, 512, SMEMB>>>(x, nullptr, wembC, nullptr,
                                      b_emb, nullptr, hbuf);                        // 3
    agg_kernel<<<NE / 4, 256>>>(hbuf, ei);                                          // 4
    gemm_tc<1><<<ggrid, 512, SMEMB>>>(hbuf, aggbuf, wl0C, wr0C,
                                      bl0, nullptr, h2buf);                         // 5 <- ncu
    zero_kernel<<<zgrid, 256>>>(0);                                                 // 6
    agg_kernel<<<NE / 4, 256>>>(h2buf, ei);                                         // 7
    gemm_tc<1><<<ggrid, 512, SMEMB>>>(h2buf, aggbuf, wl1C, wr1C,
                                      bl1, nullptr, hbuf);                          // 8
    comb_kernel<<<NL * 64 / 256, 256>>>(hbuf, sidx, didx);                          // 9
    gemm_tc<2><<<lgrid, 512, SMEMB>>>(combbuf, nullptr, wp1C, nullptr,
                                      bp1, wp2, nullptr);                           // 10
    linkfin_kernel<<<NL / 256, 256>>>(bp2, out);                                    // 11
}

// round 13
// speedup vs baseline: 17.7748x; 1.1460x over previous
// R13: double-buffered software pipeline in gemm_tc:
//  - W tiles via cp.async.cg directly into swizzled smem (async, no regs)
//  - A tiles register-prefetched in 2 half-tiles interleaved with mma steps
//  - one __syncthreads per chunk (was 2), smem 2x64KB ping-pong
#include <cuda_runtime.h>
#include <cuda_fp16.h>
#include <math.h>
#include <stdint.h>

#define NN   100000
#define NE   500000
#define FEATD 128
#define HIDD  256
#define NL   16384

// ---------------- persistent scratch ------------------------------------------
__device__ float g_deg[NN];
__device__ float g_h  [(size_t)NN * HIDD];
__device__ float g_agg[(size_t)NN * HIDD];
__device__ float g_h2 [(size_t)NN * HIDD];
__device__ float g_comb[(size_t)NL * 4 * HIDD];
__device__ float g_lacc[NL];
__device__ int   g_is64;

// fp16 weights (plain, not split — A is the split operand)
__device__ __half g_wembC[HIDD*FEATD];
__device__ __half g_wl0C[HIDD*HIDD];
__device__ __half g_wr0C[HIDD*HIDD];
__device__ __half g_wl1C[HIDD*HIDD];
__device__ __half g_wr1C[HIDD*HIDD];
__device__ __half g_wp1C[HIDD*4*HIDD];

// ---------------- helpers -------------------------------------------------------
__device__ __forceinline__ uint32_t smem_u32(const void* p) {
    uint32_t a;
    asm("{ .reg .u64 t; cvta.to.shared.u64 t, %1; cvt.u32.u64 %0, t; }"
        : "=r"(a) : "l"(p));
    return a;
}
static __device__ __forceinline__ uint32_t swz(uint32_t x) {
    return x ^ ((x >> 3) & 0x70);
}
__device__ __forceinline__ void split2h(float a, float b, uint32_t& hi, uint32_t& lo) {
    __half ha = __float2half(a), hb = __float2half(b);
    __half la = __float2half(a - __half2float(ha));
    __half lb = __float2half(b - __half2float(hb));
    hi = ((uint32_t)__half_as_ushort(hb) << 16) | __half_as_ushort(ha);
    lo = ((uint32_t)__half_as_ushort(lb) << 16) | __half_as_ushort(la);
}
__device__ __forceinline__ long long idx_at(const void* p, long long i, int is64) {
    if (is64) return ((const long long*)p)[i];
    return (long long)((const int*)p)[i];
}
__device__ __forceinline__ void ldmx4(uint32_t* r, uint32_t a) {
    asm volatile("ldmatrix.sync.aligned.m8n8.x4.shared.b16 {%0,%1,%2,%3}, [%4];"
                 : "=r"(r[0]), "=r"(r[1]), "=r"(r[2]), "=r"(r[3]) : "r"(a));
}
__device__ __forceinline__ void cp16(uint32_t dst, const void* src) {
    asm volatile("cp.async.cg.shared.global [%0], [%1], 16;"
                 :: "r"(dst), "l"(src));
}
#define CP_COMMIT() asm volatile("cp.async.commit_group;" ::: "memory")
#define CP_WAIT0()  asm volatile("cp.async.wait_group 0;" ::: "memory")
#define MMA_F16(d, a, b) \
    asm volatile("mma.sync.aligned.m16n8k16.row.col.f32.f16.f16.f32 " \
        "{%0,%1,%2,%3}, {%4,%5,%6,%7}, {%8,%9}, {%0,%1,%2,%3};" \
        : "+f"((d)[0]), "+f"((d)[1]), "+f"((d)[2]), "+f"((d)[3]) \
        : "r"((a)[0]), "r"((a)[1]), "r"((a)[2]), "r"((a)[3]), \
          "r"((b)[0]), "r"((b)[1]))

// ---------------- prep: detect + all weight conversions (1 launch) --------------
__global__ void prep_kernel(const void* ei,
                            const float* __restrict__ wemb,
                            const float* __restrict__ wl0, const float* __restrict__ wr0,
                            const float* __restrict__ wl1, const float* __restrict__ wr1,
                            const float* __restrict__ wp1) {
    int i = blockIdx.x * 256 + threadIdx.x;
    if (i == 0) {
        const unsigned* w = (const unsigned*)ei;
        int zeros = 0;
        for (int j = 1; j < 128; j += 2) zeros += (w[j] == 0u);
        g_is64 = (zeros >= 50) ? 1 : 0;
    }
    if (i < 32768)       g_wembC[i]          = __float2half(wemb[i]);
    else if (i < 98304)  g_wl0C[i - 32768]   = __float2half(wl0[i - 32768]);
    else if (i < 163840) g_wr0C[i - 98304]   = __float2half(wr0[i - 98304]);
    else if (i < 229376) g_wl1C[i - 163840]  = __float2half(wl1[i - 163840]);
    else if (i < 294912) g_wr1C[i - 229376]  = __float2half(wr1[i - 229376]);
    else if (i < 557056) g_wp1C[i - 294912]  = __float2half(wp1[i - 294912]);
}

// ---------------- misc small kernels -------------------------------------------
__global__ void zero_kernel(int with_deg) {
    long long i = (long long)blockIdx.x * blockDim.x + threadIdx.x;
    if (i < (long long)NN * HIDD / 4)
        ((float4*)g_agg)[i] = make_float4(0.f, 0.f, 0.f, 0.f);
    if (with_deg && i < NN) g_deg[i]  = 0.f;
    if (with_deg && i < NL) g_lacc[i] = 0.f;
}

__global__ void deg_kernel(const void* ei) {
    int e = blockIdx.x * blockDim.x + threadIdx.x;
    if (e < NE) {
        long long d = idx_at(ei, (long long)NE + e, g_is64);
        atomicAdd(&g_deg[d], 1.f);
    }
}

__global__ __launch_bounds__(256) void agg_kernel(const float* __restrict__ h,
                                                  const void* ei) {
    int e = blockIdx.x * 4 + (threadIdx.x >> 6);
    if (e >= NE) return;
    int lane = threadIdx.x & 63;
    int is64 = g_is64;
    long long s = idx_at(ei, e, is64);
    long long d = idx_at(ei, (long long)NE + e, is64);
    const float4 v = *(const float4*)(h + (size_t)s * HIDD + lane * 4);
    float* dp = g_agg + (size_t)d * HIDD + lane * 4;
    asm volatile("red.global.add.v4.f32 [%0], {%1,%2,%3,%4};"
                 :: "l"(dp), "f"(v.x), "f"(v.y), "f"(v.z), "f"(v.w) : "memory");
}

__global__ __launch_bounds__(256) void comb_kernel(const float* __restrict__ h,
                                                   const void* sp, const void* dp) {
    int t = blockIdx.x * 256 + threadIdx.x;   // NL*64 total
    int l = t >> 6, q = t & 63;
    int is64 = g_is64;
    long long si = idx_at(sp, l, is64);
    long long di = idx_at(dp, l, is64);
    float4 s4 = *(const float4*)(h + (size_t)si * HIDD + q * 4);
    float4 d4 = *(const float4*)(h + (size_t)di * HIDD + q * 4);
    float* row = g_comb + (size_t)l * 1024;
    *(float4*)(row + q * 4)       = s4;
    *(float4*)(row + 256 + q * 4) = d4;
    *(float4*)(row + 512 + q * 4) = make_float4(s4.x*d4.x, s4.y*d4.y, s4.z*d4.z, s4.w*d4.w);
    *(float4*)(row + 768 + q * 4) = make_float4(fabsf(s4.x-d4.x), fabsf(s4.y-d4.y),
                                                fabsf(s4.z-d4.z), fabsf(s4.w-d4.w));
}

__global__ void linkfin_kernel(const float* __restrict__ bp2, float* __restrict__ out) {
    int i = blockIdx.x * 256 + threadIdx.x;
    if (i < NL) out[i] = 1.f / (1.f + expf(-(g_lacc[i] + bp2[0])));
}

// ---------------- pipelined mma.sync split-fp16 GEMM, BN=256 --------------------
// D[128, 256] = A[128,K] @ W[256,K]^T,  2 products: Ah*W + Al*W (W plain fp16)
// 512 threads, 4x4 warp grid, 32x64 warp tiles, double-buffered smem.
// MODE 0: embed (K=128) | MODE 1: sage (K=2x256) | MODE 2: link (K=1024)

#define SA_H   0
#define SA_L   16384
#define SW_    32768
#define BUFSZ  65536          // one buffer: A_H 16K + A_L 16K + W 32K
#define S_MISC 131072
#define SMEMB  (S_MISC + 512 + 1024)

template <int MODE>
__global__ __launch_bounds__(512, 1) void gemm_tc(
    const float* __restrict__ A, const float* __restrict__ Aagg,
    const __half* __restrict__ W1, const __half* __restrict__ W2,
    const float* __restrict__ bias, const float* __restrict__ wp2,
    float* __restrict__ outp)
{
    extern __shared__ char smraw[];
    char* smc = (char*)(((uintptr_t)smraw + 1023) & ~(uintptr_t)1023);
    const uint32_t sbase = smem_u32(smc);
    const int tid = threadIdx.x;
    const int wid = tid >> 5, l = tid & 31;
    const int wm = wid >> 2, wn = wid & 3;       // 4 x 4 warp grid
    const int row0 = blockIdx.x * 128;

    constexpr int NCH = (MODE == 0) ? 2 : (MODE == 1) ? 8 : 16;
    constexpr int KA  = (MODE == 0) ? FEATD : (MODE == 1) ? HIDD : 1024;

    float* invd_s = (float*)(smc + S_MISC);
    if (MODE == 1 && tid < 128) {
        int row = row0 + tid;
        invd_s[tid] = (row < NN) ? 1.f / (g_deg[row] + 1.f) : 0.f;
    }
    if (MODE == 1) __syncthreads();

    float acc[2][8][4];
#pragma unroll
    for (int mt = 0; mt < 2; mt++)
#pragma unroll
        for (int nt = 0; nt < 8; nt++)
#pragma unroll
            for (int j = 0; j < 4; j++) acc[mt][nt][j] = 0.f;

    // ---- producer helpers (capture locals) ----
    float4 phv[2], pav[2];   // prefetch registers for one A half-tile

    auto issueW = [&](int c, int b) {
        const __half* W = (MODE == 1 && c >= 4) ? W2 : W1;
        const int colbase = (MODE == 1) ? ((c & 3) * 64) : (c * 64);
#pragma unroll
        for (int j = 0; j < 4; j++) {
            const int id  = j * 512 + tid;
            const int r   = id >> 3, c16 = id & 7;
            cp16(sbase + b * BUFSZ + SW_ + swz(r * 128 + c16 * 16),
                 W + (size_t)r * KA + colbase + c16 * 8);
        }
        CP_COMMIT();
    };
    auto loadA = [&](int c, int h) {
        const int colbase = (MODE == 1) ? ((c & 3) * 64) : (c * 64);
#pragma unroll
        for (int i = 0; i < 2; i++) {
            const int id = (h * 2 + i) * 512 + tid;
            const int r  = id >> 4, c4 = id & 15;
            const bool rv = (MODE == 2) || (row0 + r < NN);
            phv[i] = make_float4(0.f, 0.f, 0.f, 0.f);
            pav[i] = make_float4(0.f, 0.f, 0.f, 0.f);
            if (rv) {
                const size_t abase = (size_t)(row0 + r) * KA + colbase + c4 * 4;
                phv[i] = *(const float4*)(A + abase);
                if (MODE == 1 && c < 4) pav[i] = *(const float4*)(Aagg + abase);
            }
        }
    };
    auto storeA = [&](int c, int h, int b) {
#pragma unroll
        for (int i = 0; i < 2; i++) {
            const int id = (h * 2 + i) * 512 + tid;
            const int r  = id >> 4, c4 = id & 15;
            float4 v = phv[i];
            if (MODE == 1 && c < 4) {
                const float iv = invd_s[r];
                v = make_float4((pav[i].x + v.x) * iv, (pav[i].y + v.y) * iv,
                                (pav[i].z + v.z) * iv, (pav[i].w + v.w) * iv);
            }
            uint32_t h0, l0, h1, l1;
            split2h(v.x, v.y, h0, l0);
            split2h(v.z, v.w, h1, l1);
            const uint32_t s = b * BUFSZ + swz(r * 128 + c4 * 8);
            *(uint2*)(smc + SA_H + s) = make_uint2(h0, h1);
            *(uint2*)(smc + SA_L + s) = make_uint2(l0, l1);
        }
    };
    auto mma2 = [&](int b, int kk0) {
        const uint32_t ab = sbase + b * BUFSZ;
#pragma unroll
        for (int kk = kk0; kk < kk0 + 2; kk++) {
            const uint32_t kbyte = kk * 32;
            uint32_t ah[2][4], al[2][4];
#pragma unroll
            for (int mt = 0; mt < 2; mt++) {
                uint32_t off = swz((wm * 32 + mt * 16 + (l & 15)) * 128 +
                                   kbyte + ((l >> 4) << 4));
                ldmx4(ah[mt], ab + SA_H + off);
                ldmx4(al[mt], ab + SA_L + off);
            }
            uint32_t bf[8][2];
#pragma unroll
            for (int ntb = 0; ntb < 4; ntb++) {
                const int nt2 = ntb * 2;
                uint32_t off = swz((wn * 64 + (nt2 + ((l >> 4) & 1)) * 8 + (l & 7)) * 128
                                   + kbyte + (((l >> 3) & 1) << 4));
                uint32_t r[4];
                ldmx4(r, ab + SW_ + off);
                bf[nt2][0] = r[0]; bf[nt2][1] = r[1];
                bf[nt2 + 1][0] = r[2]; bf[nt2 + 1][1] = r[3];
            }
#pragma unroll
            for (int nt = 0; nt < 8; nt++)
#pragma unroll
                for (int mt = 0; mt < 2; mt++) {
                    MMA_F16(acc[mt][nt], ah[mt], bf[nt]);
                    MMA_F16(acc[mt][nt], al[mt], bf[nt]);
                }
        }
    };

    // ---- prologue: produce chunk 0 into buffer 0 ----
    issueW(0, 0);
    loadA(0, 0); storeA(0, 0, 0);
    loadA(0, 1); storeA(0, 1, 0);
    CP_WAIT0();
    __syncthreads();

    // ---- pipelined main loop: 1 sync per chunk ----
    for (int c = 0; c < NCH; c++) {
        const int b = c & 1, nb = b ^ 1;
        const bool pf = (c + 1 < NCH);
        if (pf) { issueW(c + 1, nb); loadA(c + 1, 0); }
        mma2(b, 0);
        if (pf) { storeA(c + 1, 0, nb); loadA(c + 1, 1); }
        mma2(b, 2);
        if (pf) { storeA(c + 1, 1, nb); }
        CP_WAIT0();
        __syncthreads();
    }

    // ---- epilogue ----
    if (MODE == 2) {
#pragma unroll
        for (int mt = 0; mt < 2; mt++) {
            int rloc = wm * 32 + mt * 16 + (l >> 2);
            float s0 = 0.f, s1 = 0.f;
#pragma unroll
            for (int nt = 0; nt < 8; nt++) {
                int col = wn * 64 + nt * 8 + (l & 3) * 2;
                float b0 = bias[col], b1 = bias[col + 1];
                float w0 = wp2[col],  w1 = wp2[col + 1];
                s0 += fmaxf(acc[mt][nt][0] + b0, 0.f) * w0
                    + fmaxf(acc[mt][nt][1] + b1, 0.f) * w1;
                s1 += fmaxf(acc[mt][nt][2] + b0, 0.f) * w0
                    + fmaxf(acc[mt][nt][3] + b1, 0.f) * w1;
            }
            atomicAdd(&g_lacc[row0 + rloc], s0);
            atomicAdd(&g_lacc[row0 + rloc + 8], s1);
        }
    } else {
#pragma unroll
        for (int mt = 0; mt < 2; mt++) {
            int r0 = row0 + wm * 32 + mt * 16 + (l >> 2);
#pragma unroll
            for (int nt = 0; nt < 8; nt++) {
                int col = wn * 64 + nt * 8 + (l & 3) * 2;
                float b0 = bias[col], b1 = bias[col + 1];
                float v0 = acc[mt][nt][0] + b0, v1 = acc[mt][nt][1] + b1;
                float v2 = acc[mt][nt][2] + b0, v3 = acc[mt][nt][3] + b1;
                if (MODE == 1) {
                    v0 = fmaxf(v0, 0.f); v1 = fmaxf(v1, 0.f);
                    v2 = fmaxf(v2, 0.f); v3 = fmaxf(v3, 0.f);
                }
                if (r0 < NN)
                    *(float2*)(outp + (size_t)r0 * HIDD + col) = make_float2(v0, v1);
                if (r0 + 8 < NN)
                    *(float2*)(outp + (size_t)(r0 + 8) * HIDD + col) = make_float2(v2, v3);
            }
        }
    }
}

// ---------------- launcher ------------------------------------------------------
extern "C" void kernel_launch(void* const* d_in, const int* in_sizes, int n_in,
                              void* d_out, int out_size) {
    (void)in_sizes; (void)n_in; (void)out_size;
    const float* x     = (const float*)d_in[0];
    const void*  ei    = d_in[1];
    const void*  sidx  = d_in[3];
    const void*  didx  = d_in[4];
    const float* w_emb = (const float*)d_in[5];
    const float* b_emb = (const float*)d_in[6];
    const float* wl0 = (const float*)d_in[8];
    const float* bl0 = (const float*)d_in[9];
    const float* wr0 = (const float*)d_in[10];
    const float* wl1 = (const float*)d_in[13];
    const float* bl1 = (const float*)d_in[14];
    const float* wr1 = (const float*)d_in[15];
    const float* wp1 = (const float*)d_in[18];
    const float* bp1 = (const float*)d_in[19];
    const float* wp2 = (const float*)d_in[20];
    const float* bp2 = (const float*)d_in[21];
    float* out = (float*)d_out;

    cudaFuncSetAttribute(gemm_tc<0>, cudaFuncAttributeMaxDynamicSharedMemorySize, SMEMB);
    cudaFuncSetAttribute(gemm_tc<1>, cudaFuncAttributeMaxDynamicSharedMemorySize, SMEMB);
    cudaFuncSetAttribute(gemm_tc<2>, cudaFuncAttributeMaxDynamicSharedMemorySize, SMEMB);

    __half *wembC, *wl0C, *wr0C, *wl1C, *wr1C, *wp1C;
    float *hbuf, *aggbuf, *h2buf, *combbuf;
    cudaGetSymbolAddress((void**)&wembC, g_wembC);
    cudaGetSymbolAddress((void**)&wl0C, g_wl0C);
    cudaGetSymbolAddress((void**)&wr0C, g_wr0C);
    cudaGetSymbolAddress((void**)&wl1C, g_wl1C);
    cudaGetSymbolAddress((void**)&wr1C, g_wr1C);
    cudaGetSymbolAddress((void**)&wp1C, g_wp1C);
    cudaGetSymbolAddress((void**)&hbuf, g_h);
    cudaGetSymbolAddress((void**)&aggbuf, g_agg);
    cudaGetSymbolAddress((void**)&h2buf, g_h2);
    cudaGetSymbolAddress((void**)&combbuf, g_comb);

    const int zgrid = (NN * HIDD / 4 + 255) / 256;
    const int ggrid = (NN + 127) / 128;      // 782
    const int lgrid = NL / 128;              // 128

    // launch order chosen so ncu (-s 5 -c 1) captures a GEMM
    prep_kernel<<<(557056 + 255) / 256, 256>>>(ei, w_emb, wl0, wr0, wl1, wr1, wp1); // 0
    zero_kernel<<<zgrid, 256>>>(1);                                                 // 1
    deg_kernel<<<(NE + 255) / 256, 256>>>(ei);                                      // 2
    gemm_tc<0><<<ggrid, 512, SMEMB>>>(x, nullptr, wembC, nullptr,
                                      b_emb, nullptr, hbuf);                        // 3
    agg_kernel<<<NE / 4, 256>>>(hbuf, ei);                                          // 4
    gemm_tc<1><<<ggrid, 512, SMEMB>>>(hbuf, aggbuf, wl0C, wr0C,
                                      bl0, nullptr, h2buf);                         // 5 <- ncu
    zero_kernel<<<zgrid, 256>>>(0);                                                 // 6
    agg_kernel<<<NE / 4, 256>>>(h2buf, ei);                                         // 7
    gemm_tc<1><<<ggrid, 512, SMEMB>>>(h2buf, aggbuf, wl1C, wr1C,
                                      bl1, nullptr, hbuf);                          // 8
    comb_kernel<<<NL * 64 / 256, 256>>>(hbuf, sidx, didx);                          // 9
    gemm_tc<2><<<lgrid, 512, SMEMB>>>(combbuf, nullptr, wp1C, nullptr,
                                      bp1, wp2, nullptr);                           // 10
    linkfin_kernel<<<NL / 256, 256>>>(bp2, out);                                    // 11
}

// round 14
// speedup vs baseline: 24.3886x; 1.3721x over previous
// R14: all-fp16 activations. h/h2/agg/comb stored fp16; f16x2 vector RED for
// aggregation; single-product fp16 mma (no A split); MODE1 wr-chunks and MODE2
// A tiles via cp.async with no conversion. Pipeline structure from R13 kept.
#include <cuda_runtime.h>
#include <cuda_fp16.h>
#include <math.h>
#include <stdint.h>

#define NN   100000
#define NE   500000
#define FEATD 128
#define HIDD  256
#define NL   16384

// ---------------- persistent scratch ------------------------------------------
__device__ float  g_deg[NN];
__device__ __half g_h  [(size_t)NN * HIDD];
__device__ __half g_agg[(size_t)NN * HIDD];
__device__ __half g_h2 [(size_t)NN * HIDD];
__device__ __half g_comb[(size_t)NL * 4 * HIDD];
__device__ float  g_lacc[NL];
__device__ int    g_is64;

__device__ __half g_wembC[HIDD*FEATD];
__device__ __half g_wl0C[HIDD*HIDD];
__device__ __half g_wr0C[HIDD*HIDD];
__device__ __half g_wl1C[HIDD*HIDD];
__device__ __half g_wr1C[HIDD*HIDD];
__device__ __half g_wp1C[HIDD*4*HIDD];

// ---------------- helpers -------------------------------------------------------
__device__ __forceinline__ uint32_t smem_u32(const void* p) {
    uint32_t a;
    asm("{ .reg .u64 t; cvta.to.shared.u64 t, %1; cvt.u32.u64 %0, t; }"
        : "=r"(a) : "l"(p));
    return a;
}
static __device__ __forceinline__ uint32_t swz(uint32_t x) {
    return x ^ ((x >> 3) & 0x70);
}
__device__ __forceinline__ long long idx_at(const void* p, long long i, int is64) {
    if (is64) return ((const long long*)p)[i];
    return (long long)((const int*)p)[i];
}
__device__ __forceinline__ void ldmx4(uint32_t* r, uint32_t a) {
    asm volatile("ldmatrix.sync.aligned.m8n8.x4.shared.b16 {%0,%1,%2,%3}, [%4];"
                 : "=r"(r[0]), "=r"(r[1]), "=r"(r[2]), "=r"(r[3]) : "r"(a));
}
__device__ __forceinline__ void cp16(uint32_t dst, const void* src) {
    asm volatile("cp.async.cg.shared.global [%0], [%1], 16;"
                 :: "r"(dst), "l"(src));
}
#define CP_COMMIT() asm volatile("cp.async.commit_group;" ::: "memory")
#define CP_WAIT0()  asm volatile("cp.async.wait_group 0;" ::: "memory")
#define MMA_F16(d, a, b) \
    asm volatile("mma.sync.aligned.m16n8k16.row.col.f32.f16.f16.f32 " \
        "{%0,%1,%2,%3}, {%4,%5,%6,%7}, {%8,%9}, {%0,%1,%2,%3};" \
        : "+f"((d)[0]), "+f"((d)[1]), "+f"((d)[2]), "+f"((d)[3]) \
        : "r"((a)[0]), "r"((a)[1]), "r"((a)[2]), "r"((a)[3]), \
          "r"((b)[0]), "r"((b)[1]))

// ---------------- prep ----------------------------------------------------------
__global__ void prep_kernel(const void* ei,
                            const float* __restrict__ wemb,
                            const float* __restrict__ wl0, const float* __restrict__ wr0,
                            const float* __restrict__ wl1, const float* __restrict__ wr1,
                            const float* __restrict__ wp1) {
    int i = blockIdx.x * 256 + threadIdx.x;
    if (i == 0) {
        const unsigned* w = (const unsigned*)ei;
        int zeros = 0;
        for (int j = 1; j < 128; j += 2) zeros += (w[j] == 0u);
        g_is64 = (zeros >= 50) ? 1 : 0;
    }
    if (i < 32768)       g_wembC[i]          = __float2half(wemb[i]);
    else if (i < 98304)  g_wl0C[i - 32768]   = __float2half(wl0[i - 32768]);
    else if (i < 163840) g_wr0C[i - 98304]   = __float2half(wr0[i - 98304]);
    else if (i < 229376) g_wl1C[i - 163840]  = __float2half(wl1[i - 163840]);
    else if (i < 294912) g_wr1C[i - 229376]  = __float2half(wr1[i - 229376]);
    else if (i < 557056) g_wp1C[i - 294912]  = __float2half(wp1[i - 294912]);
}

// ---------------- misc small kernels -------------------------------------------
__global__ void zero_kernel(int with_deg) {
    long long i = (long long)blockIdx.x * blockDim.x + threadIdx.x;   // uint4 units
    if (i < (long long)NN * HIDD / 8)
        ((uint4*)g_agg)[i] = make_uint4(0u, 0u, 0u, 0u);
    if (with_deg && i < NN) g_deg[i]  = 0.f;
    if (with_deg && i < NL) g_lacc[i] = 0.f;
}

__global__ void deg_kernel(const void* ei) {
    int e = blockIdx.x * blockDim.x + threadIdx.x;
    if (e < NE) {
        long long d = idx_at(ei, (long long)NE + e, g_is64);
        atomicAdd(&g_deg[d], 1.f);
    }
}

// 8 edges / block, 32 lanes per edge; 16B gather + v4.f16x2 vector RED.
__global__ __launch_bounds__(256) void agg_kernel(const __half* __restrict__ h,
                                                  const void* ei) {
    int e = blockIdx.x * 8 + (threadIdx.x >> 5);
    if (e >= NE) return;
    int lane = threadIdx.x & 31;
    int is64 = g_is64;
    long long s = idx_at(ei, e, is64);
    long long d = idx_at(ei, (long long)NE + e, is64);
    uint4 v = *(const uint4*)(h + (size_t)s * HIDD + lane * 8);
    __half* dp = g_agg + (size_t)d * HIDD + lane * 8;
    asm volatile("red.global.add.noftz.v4.f16x2 [%0], {%1,%2,%3,%4};"
                 :: "l"(dp), "r"(v.x), "r"(v.y), "r"(v.z), "r"(v.w) : "memory");
}

__global__ __launch_bounds__(256) void comb_kernel(const __half* __restrict__ h,
                                                   const void* sp, const void* dp) {
    int t = blockIdx.x * 256 + threadIdx.x;   // NL*32 total
    int l = t >> 5, q = t & 31;
    int is64 = g_is64;
    long long si = idx_at(sp, l, is64);
    long long di = idx_at(dp, l, is64);
    uint4 s4 = *(const uint4*)(h + (size_t)si * HIDD + q * 8);
    uint4 d4 = *(const uint4*)(h + (size_t)di * HIDD + q * 8);
    uint4 m4, a4;
    const __half2* s2 = (const __half2*)&s4;
    const __half2* d2 = (const __half2*)&d4;
    __half2* m2 = (__half2*)&m4;
    __half2* a2 = (__half2*)&a4;
#pragma unroll
    for (int k = 0; k < 4; k++) {
        m2[k] = __hmul2(s2[k], d2[k]);
        a2[k] = __habs2(__hsub2(s2[k], d2[k]));
    }
    __half* row = g_comb + (size_t)l * 1024;
    *(uint4*)(row + q * 8)       = s4;
    *(uint4*)(row + 256 + q * 8) = d4;
    *(uint4*)(row + 512 + q * 8) = m4;
    *(uint4*)(row + 768 + q * 8) = a4;
}

__global__ void linkfin_kernel(const float* __restrict__ bp2, float* __restrict__ out) {
    int i = blockIdx.x * 256 + threadIdx.x;
    if (i < NL) out[i] = 1.f / (1.f + expf(-(g_lacc[i] + bp2[0])));
}

// ---------------- pipelined fp16 GEMM, BN=256, single product -------------------
// D[128, 256] = A[128,K] @ W[256,K]^T, fp32 accum.
// MODE 0: embed (A = x fp32, K=128; out fp16 = D + bias)
// MODE 1: sage  (K=2x256: A = mean (conv from fp16 h+agg) then h (async);
//                out fp16 = relu(D + bias))
// MODE 2: link  (A = comb fp16 async, K=1024; epilogue atomicAdd(relu(D+b).wp2))

#define SA_    0
#define SW_    16384
#define BUFSZ  49152          // A 16K + W 32K
#define S_MISC 98304
#define SMEMB  (S_MISC + 512 + 1024)

template <int MODE>
__global__ __launch_bounds__(512, 1) void gemm_tc(
    const float* __restrict__ Af, const __half* __restrict__ Ah,
    const __half* __restrict__ W1, const __half* __restrict__ W2,
    const float* __restrict__ bias, const float* __restrict__ wp2,
    __half* __restrict__ outp)
{
    extern __shared__ char smraw[];
    char* smc = (char*)(((uintptr_t)smraw + 1023) & ~(uintptr_t)1023);
    const uint32_t sbase = smem_u32(smc);
    const int tid = threadIdx.x;
    const int wid = tid >> 5, l = tid & 31;
    const int wm = wid >> 2, wn = wid & 3;       // 4 x 4 warp grid
    const int row0 = blockIdx.x * 128;

    constexpr int NCH = (MODE == 0) ? 2 : (MODE == 1) ? 8 : 16;
    constexpr int KA  = (MODE == 0) ? FEATD : (MODE == 1) ? HIDD : 1024;

    float* invd_s = (float*)(smc + S_MISC);
    if (MODE == 1 && tid < 128) {
        int row = row0 + tid;
        invd_s[tid] = (row < NN) ? 1.f / (g_deg[row] + 1.f) : 0.f;
    }
    if (MODE == 1) __syncthreads();

    float acc[2][8][4];
#pragma unroll
    for (int mt = 0; mt < 2; mt++)
#pragma unroll
        for (int nt = 0; nt < 8; nt++)
#pragma unroll
            for (int j = 0; j < 4; j++) acc[mt][nt][j] = 0.f;

    float4 phv[2];            // MODE 0 prefetch
    uint4  pqh, pqa;          // MODE 1 mean-path prefetch

    auto needs_conv = [&](int c) { return MODE == 0 || (MODE == 1 && c < 4); };

    auto issueW = [&](int c, int b) {
        const __half* W = (MODE == 1 && c >= 4) ? W2 : W1;
        const int colbase = (MODE == 1) ? ((c & 3) * 64) : (c * 64);
#pragma unroll
        for (int j = 0; j < 4; j++) {
            const int id  = j * 512 + tid;
            const int r   = id >> 3, c16 = id & 7;
            cp16(sbase + b * BUFSZ + SW_ + swz(r * 128 + c16 * 16),
                 W + (size_t)r * KA + colbase + c16 * 8);
        }
    };
    // async A (MODE 1 c>=4 from h; MODE 2 from comb): 1024 uint4 slots
    auto issueA = [&](int c, int b) {
        const int colbase = (MODE == 1) ? ((c & 3) * 64) : (c * 64);
#pragma unroll
        for (int j = 0; j < 2; j++) {
            const int id  = j * 512 + tid;
            const int r   = id >> 3, c16 = id & 7;
            const uint32_t dst = sbase + b * BUFSZ + SA_ + swz(r * 128 + c16 * 16);
            if (MODE == 2 || row0 + r < NN)
                cp16(dst, Ah + (size_t)(row0 + r) * KA + colbase + c16 * 8);
            else
                *(uint4*)(smc + (dst - sbase)) = make_uint4(0u, 0u, 0u, 0u);
        }
    };
    auto loadA = [&](int c, int h) {
        const int colbase = (MODE == 1) ? ((c & 3) * 64) : (c * 64);
        if (MODE == 0) {
#pragma unroll
            for (int i = 0; i < 2; i++) {
                const int id = (h * 2 + i) * 512 + tid;
                const int r  = id >> 4, c4 = id & 15;
                phv[i] = make_float4(0.f, 0.f, 0.f, 0.f);
                if (row0 + r < NN)
                    phv[i] = *(const float4*)(Af + (size_t)(row0 + r) * KA + colbase + c4 * 4);
            }
        } else {   // MODE 1 mean path
            const int id = h * 512 + tid;
            const int r  = id >> 3, c8 = id & 7;
            pqh = make_uint4(0u, 0u, 0u, 0u);
            pqa = make_uint4(0u, 0u, 0u, 0u);
            if (row0 + r < NN) {
                const size_t off = (size_t)(row0 + r) * HIDD + colbase + c8 * 8;
                pqh = *(const uint4*)(Ah + off);
                pqa = *(const uint4*)(g_agg + off);
            }
        }
    };
    auto storeA = [&](int c, int h, int b) {
        if (MODE == 0) {
#pragma unroll
            for (int i = 0; i < 2; i++) {
                const int id = (h * 2 + i) * 512 + tid;
                const int r  = id >> 4, c4 = id & 15;
                uint2 o;
                ((__half2*)&o)[0] = __floats2half2_rn(phv[i].x, phv[i].y);
                ((__half2*)&o)[1] = __floats2half2_rn(phv[i].z, phv[i].w);
                *(uint2*)(smc + b * BUFSZ + SA_ + swz(r * 128 + c4 * 8)) = o;
            }
        } else {
            const int id = h * 512 + tid;
            const int r  = id >> 3, c8 = id & 7;
            const float iv = invd_s[r];
            uint4 o;
            const __half2* ph = (const __half2*)&pqh;
            const __half2* pa = (const __half2*)&pqa;
            __half2* po = (__half2*)&o;
#pragma unroll
            for (int k = 0; k < 4; k++) {
                float2 hf = __half22float2(ph[k]);
                float2 af = __half22float2(pa[k]);
                po[k] = __floats2half2_rn((af.x + hf.x) * iv, (af.y + hf.y) * iv);
            }
            *(uint4*)(smc + b * BUFSZ + SA_ + swz(r * 128 + c8 * 16)) = o;
        }
    };
    auto mma2 = [&](int b, int kk0) {
        const uint32_t ab = sbase + b * BUFSZ;
#pragma unroll
        for (int kk = kk0; kk < kk0 + 2; kk++) {
            const uint32_t kbyte = kk * 32;
            uint32_t ar[2][4];
#pragma unroll
            for (int mt = 0; mt < 2; mt++) {
                uint32_t off = swz((wm * 32 + mt * 16 + (l & 15)) * 128 +
                                   kbyte + ((l >> 4) << 4));
                ldmx4(ar[mt], ab + SA_ + off);
            }
            uint32_t bf[8][2];
#pragma unroll
            for (int ntb = 0; ntb < 4; ntb++) {
                const int nt2 = ntb * 2;
                uint32_t off = swz((wn * 64 + (nt2 + ((l >> 4) & 1)) * 8 + (l & 7)) * 128
                                   + kbyte + (((l >> 3) & 1) << 4));
                uint32_t r[4];
                ldmx4(r, ab + SW_ + off);
                bf[nt2][0] = r[0]; bf[nt2][1] = r[1];
                bf[nt2 + 1][0] = r[2]; bf[nt2 + 1][1] = r[3];
            }
#pragma unroll
            for (int nt = 0; nt < 8; nt++)
#pragma unroll
                for (int mt = 0; mt < 2; mt++)
                    MMA_F16(acc[mt][nt], ar[mt], bf[nt]);
        }
    };

    // ---- prologue: chunk 0 into buffer 0 ----
    issueW(0, 0);
    if (needs_conv(0)) {
        loadA(0, 0); storeA(0, 0, 0);
        loadA(0, 1); storeA(0, 1, 0);
    } else {
        issueA(0, 0);
    }
    CP_COMMIT();
    CP_WAIT0();
    __syncthreads();

    // ---- pipelined main loop: 1 sync per chunk ----
    for (int c = 0; c < NCH; c++) {
        const int b = c & 1, nb = b ^ 1;
        const bool pf = (c + 1 < NCH);
        bool cv = pf && needs_conv(c + 1);
        if (pf) {
            issueW(c + 1, nb);
            if (cv) loadA(c + 1, 0); else issueA(c + 1, nb);
            CP_COMMIT();
        }
        mma2(b, 0);
        if (cv) { storeA(c + 1, 0, nb); loadA(c + 1, 1); }
        mma2(b, 2);
        if (cv) storeA(c + 1, 1, nb);
        CP_WAIT0();
        __syncthreads();
    }

    // ---- epilogue ----
    if (MODE == 2) {
#pragma unroll
        for (int mt = 0; mt < 2; mt++) {
            int rloc = wm * 32 + mt * 16 + (l >> 2);
            float s0 = 0.f, s1 = 0.f;
#pragma unroll
            for (int nt = 0; nt < 8; nt++) {
                int col = wn * 64 + nt * 8 + (l & 3) * 2;
                float b0 = bias[col], b1 = bias[col + 1];
                float w0 = wp2[col],  w1 = wp2[col + 1];
                s0 += fmaxf(acc[mt][nt][0] + b0, 0.f) * w0
                    + fmaxf(acc[mt][nt][1] + b1, 0.f) * w1;
                s1 += fmaxf(acc[mt][nt][2] + b0, 0.f) * w0
                    + fmaxf(acc[mt][nt][3] + b1, 0.f) * w1;
            }
            atomicAdd(&g_lacc[row0 + rloc], s0);
            atomicAdd(&g_lacc[row0 + rloc + 8], s1);
        }
    } else {
#pragma unroll
        for (int mt = 0; mt < 2; mt++) {
            int r0 = row0 + wm * 32 + mt * 16 + (l >> 2);
#pragma unroll
            for (int nt = 0; nt < 8; nt++) {
                int col = wn * 64 + nt * 8 + (l & 3) * 2;
                float b0 = bias[col], b1 = bias[col + 1];
                float v0 = acc[mt][nt][0] + b0, v1 = acc[mt][nt][1] + b1;
                float v2 = acc[mt][nt][2] + b0, v3 = acc[mt][nt][3] + b1;
                if (MODE == 1) {
                    v0 = fmaxf(v0, 0.f); v1 = fmaxf(v1, 0.f);
                    v2 = fmaxf(v2, 0.f); v3 = fmaxf(v3, 0.f);
                }
                if (r0 < NN)
                    *(__half2*)(outp + (size_t)r0 * HIDD + col) = __floats2half2_rn(v0, v1);
                if (r0 + 8 < NN)
                    *(__half2*)(outp + (size_t)(r0 + 8) * HIDD + col) = __floats2half2_rn(v2, v3);
            }
        }
    }
}

// ---------------- launcher ------------------------------------------------------
extern "C" void kernel_launch(void* const* d_in, const int* in_sizes, int n_in,
                              void* d_out, int out_size) {
    (void)in_sizes; (void)n_in; (void)out_size;
    const float* x     = (const float*)d_in[0];
    const void*  ei    = d_in[1];
    const void*  sidx  = d_in[3];
    const void*  didx  = d_in[4];
    const float* w_emb = (const float*)d_in[5];
    const float* b_emb = (const float*)d_in[6];
    const float* wl0 = (const float*)d_in[8];
    const float* bl0 = (const float*)d_in[9];
    const float* wr0 = (const float*)d_in[10];
    const float* wl1 = (const float*)d_in[13];
    const float* bl1 = (const float*)d_in[14];
    const float* wr1 = (const float*)d_in[15];
    const float* wp1 = (const float*)d_in[18];
    const float* bp1 = (const float*)d_in[19];
    const float* wp2 = (const float*)d_in[20];
    const float* bp2 = (const float*)d_in[21];
    float* out = (float*)d_out;

    cudaFuncSetAttribute(gemm_tc<0>, cudaFuncAttributeMaxDynamicSharedMemorySize, SMEMB);
    cudaFuncSetAttribute(gemm_tc<1>, cudaFuncAttributeMaxDynamicSharedMemorySize, SMEMB);
    cudaFuncSetAttribute(gemm_tc<2>, cudaFuncAttributeMaxDynamicSharedMemorySize, SMEMB);

    __half *wembC, *wl0C, *wr0C, *wl1C, *wr1C, *wp1C;
    __half *hbuf, *aggbuf, *h2buf, *combbuf;
    cudaGetSymbolAddress((void**)&wembC, g_wembC);
    cudaGetSymbolAddress((void**)&wl0C, g_wl0C);
    cudaGetSymbolAddress((void**)&wr0C, g_wr0C);
    cudaGetSymbolAddress((void**)&wl1C, g_wl1C);
    cudaGetSymbolAddress((void**)&wr1C, g_wr1C);
    cudaGetSymbolAddress((void**)&wp1C, g_wp1C);
    cudaGetSymbolAddress((void**)&hbuf, g_h);
    cudaGetSymbolAddress((void**)&aggbuf, g_agg);
    cudaGetSymbolAddress((void**)&h2buf, g_h2);
    cudaGetSymbolAddress((void**)&combbuf, g_comb);
    (void)aggbuf;

    const int zgrid = (NN * HIDD / 8 + 255) / 256;   // uint4 units of g_agg
    const int ggrid = (NN + 127) / 128;              // 782
    const int lgrid = NL / 128;                      // 128

    prep_kernel<<<(557056 + 255) / 256, 256>>>(ei, w_emb, wl0, wr0, wl1, wr1, wp1); // 0
    zero_kernel<<<zgrid, 256>>>(1);                                                 // 1
    deg_kernel<<<(NE + 255) / 256, 256>>>(ei);                                      // 2
    gemm_tc<0><<<ggrid, 512, SMEMB>>>(x, nullptr, wembC, nullptr,
                                      b_emb, nullptr, hbuf);                        // 3
    agg_kernel<<<NE / 8, 256>>>(hbuf, ei);                                          // 4
    gemm_tc<1><<<ggrid, 512, SMEMB>>>(nullptr, hbuf, wl0C, wr0C,
                                      bl0, nullptr, h2buf);                         // 5 <- ncu
    zero_kernel<<<zgrid, 256>>>(0);                                                 // 6
    agg_kernel<<<NE / 8, 256>>>(h2buf, ei);                                         // 7
    gemm_tc<1><<<ggrid, 512, SMEMB>>>(nullptr, h2buf, wl1C, wr1C,
                                      bl1, nullptr, hbuf);                          // 8
    comb_kernel<<<NL * 32 / 256, 256>>>(hbuf, sidx, didx);                          // 9
    gemm_tc<2><<<lgrid, 512, SMEMB>>>(nullptr, combbuf, wp1C, nullptr,
                                      bp1, wp2, nullptr);                           // 10
    linkfin_kernel<<<NL / 256, 256>>>(bp2, out);                                    // 11
}

// round 15
// speedup vs baseline: 37.4205x; 1.5343x over previous
// R15: BM=64/BN=256, 256 threads, 2 CTAs/SM (occupancy fix). Same warp-tile
// math and R14 pipeline; producer maps re-derived for 256 threads; smem
// 2x40KB ping-pong + misc.
#include <cuda_runtime.h>
#include <cuda_fp16.h>
#include <math.h>
#include <stdint.h>

#define NN   100000
#define NE   500000
#define FEATD 128
#define HIDD  256
#define NL   16384

// ---------------- persistent scratch ------------------------------------------
__device__ float  g_deg[NN];
__device__ __half g_h  [(size_t)NN * HIDD];
__device__ __half g_agg[(size_t)NN * HIDD];
__device__ __half g_h2 [(size_t)NN * HIDD];
__device__ __half g_comb[(size_t)NL * 4 * HIDD];
__device__ float  g_lacc[NL];
__device__ int    g_is64;

__device__ __half g_wembC[HIDD*FEATD];
__device__ __half g_wl0C[HIDD*HIDD];
__device__ __half g_wr0C[HIDD*HIDD];
__device__ __half g_wl1C[HIDD*HIDD];
__device__ __half g_wr1C[HIDD*HIDD];
__device__ __half g_wp1C[HIDD*4*HIDD];

// ---------------- helpers -------------------------------------------------------
__device__ __forceinline__ uint32_t smem_u32(const void* p) {
    uint32_t a;
    asm("{ .reg .u64 t; cvta.to.shared.u64 t, %1; cvt.u32.u64 %0, t; }"
        : "=r"(a) : "l"(p));
    return a;
}
static __device__ __forceinline__ uint32_t swz(uint32_t x) {
    return x ^ ((x >> 3) & 0x70);
}
__device__ __forceinline__ long long idx_at(const void* p, long long i, int is64) {
    if (is64) return ((const long long*)p)[i];
    return (long long)((const int*)p)[i];
}
__device__ __forceinline__ void ldmx4(uint32_t* r, uint32_t a) {
    asm volatile("ldmatrix.sync.aligned.m8n8.x4.shared.b16 {%0,%1,%2,%3}, [%4];"
                 : "=r"(r[0]), "=r"(r[1]), "=r"(r[2]), "=r"(r[3]) : "r"(a));
}
__device__ __forceinline__ void cp16(uint32_t dst, const void* src) {
    asm volatile("cp.async.cg.shared.global [%0], [%1], 16;"
                 :: "r"(dst), "l"(src));
}
#define CP_COMMIT() asm volatile("cp.async.commit_group;" ::: "memory")
#define CP_WAIT0()  asm volatile("cp.async.wait_group 0;" ::: "memory")
#define MMA_F16(d, a, b) \
    asm volatile("mma.sync.aligned.m16n8k16.row.col.f32.f16.f16.f32 " \
        "{%0,%1,%2,%3}, {%4,%5,%6,%7}, {%8,%9}, {%0,%1,%2,%3};" \
        : "+f"((d)[0]), "+f"((d)[1]), "+f"((d)[2]), "+f"((d)[3]) \
        : "r"((a)[0]), "r"((a)[1]), "r"((a)[2]), "r"((a)[3]), \
          "r"((b)[0]), "r"((b)[1]))

// ---------------- prep ----------------------------------------------------------
__global__ void prep_kernel(const void* ei,
                            const float* __restrict__ wemb,
                            const float* __restrict__ wl0, const float* __restrict__ wr0,
                            const float* __restrict__ wl1, const float* __restrict__ wr1,
                            const float* __restrict__ wp1) {
    int i = blockIdx.x * 256 + threadIdx.x;
    if (i == 0) {
        const unsigned* w = (const unsigned*)ei;
        int zeros = 0;
        for (int j = 1; j < 128; j += 2) zeros += (w[j] == 0u);
        g_is64 = (zeros >= 50) ? 1 : 0;
    }
    if (i < 32768)       g_wembC[i]          = __float2half(wemb[i]);
    else if (i < 98304)  g_wl0C[i - 32768]   = __float2half(wl0[i - 32768]);
    else if (i < 163840) g_wr0C[i - 98304]   = __float2half(wr0[i - 98304]);
    else if (i < 229376) g_wl1C[i - 163840]  = __float2half(wl1[i - 163840]);
    else if (i < 294912) g_wr1C[i - 229376]  = __float2half(wr1[i - 229376]);
    else if (i < 557056) g_wp1C[i - 294912]  = __float2half(wp1[i - 294912]);
}

// ---------------- misc small kernels -------------------------------------------
__global__ void zero_kernel(int with_deg) {
    long long i = (long long)blockIdx.x * blockDim.x + threadIdx.x;   // uint4 units
    if (i < (long long)NN * HIDD / 8)
        ((uint4*)g_agg)[i] = make_uint4(0u, 0u, 0u, 0u);
    if (with_deg && i < NN) g_deg[i]  = 0.f;
    if (with_deg && i < NL) g_lacc[i] = 0.f;
}

__global__ void deg_kernel(const void* ei) {
    int e = blockIdx.x * blockDim.x + threadIdx.x;
    if (e < NE) {
        long long d = idx_at(ei, (long long)NE + e, g_is64);
        atomicAdd(&g_deg[d], 1.f);
    }
}

// 8 edges / block, 32 lanes per edge; 16B gather + v4.f16x2 vector RED.
__global__ __launch_bounds__(256) void agg_kernel(const __half* __restrict__ h,
                                                  const void* ei) {
    int e = blockIdx.x * 8 + (threadIdx.x >> 5);
    if (e >= NE) return;
    int lane = threadIdx.x & 31;
    int is64 = g_is64;
    long long s = idx_at(ei, e, is64);
    long long d = idx_at(ei, (long long)NE + e, is64);
    uint4 v = *(const uint4*)(h + (size_t)s * HIDD + lane * 8);
    __half* dp = g_agg + (size_t)d * HIDD + lane * 8;
    asm volatile("red.global.add.noftz.v4.f16x2 [%0], {%1,%2,%3,%4};"
                 :: "l"(dp), "r"(v.x), "r"(v.y), "r"(v.z), "r"(v.w) : "memory");
}

__global__ __launch_bounds__(256) void comb_kernel(const __half* __restrict__ h,
                                                   const void* sp, const void* dp) {
    int t = blockIdx.x * 256 + threadIdx.x;   // NL*32 total
    int l = t >> 5, q = t & 31;
    int is64 = g_is64;
    long long si = idx_at(sp, l, is64);
    long long di = idx_at(dp, l, is64);
    uint4 s4 = *(const uint4*)(h + (size_t)si * HIDD + q * 8);
    uint4 d4 = *(const uint4*)(h + (size_t)di * HIDD + q * 8);
    uint4 m4, a4;
    const __half2* s2 = (const __half2*)&s4;
    const __half2* d2 = (const __half2*)&d4;
    __half2* m2 = (__half2*)&m4;
    __half2* a2 = (__half2*)&a4;
#pragma unroll
    for (int k = 0; k < 4; k++) {
        m2[k] = __hmul2(s2[k], d2[k]);
        a2[k] = __habs2(__hsub2(s2[k], d2[k]));
    }
    __half* row = g_comb + (size_t)l * 1024;
    *(uint4*)(row + q * 8)       = s4;
    *(uint4*)(row + 256 + q * 8) = d4;
    *(uint4*)(row + 512 + q * 8) = m4;
    *(uint4*)(row + 768 + q * 8) = a4;
}

__global__ void linkfin_kernel(const float* __restrict__ bp2, float* __restrict__ out) {
    int i = blockIdx.x * 256 + threadIdx.x;
    if (i < NL) out[i] = 1.f / (1.f + expf(-(g_lacc[i] + bp2[0])));
}

// ---------------- pipelined fp16 GEMM, BM=64 BN=256, 2 CTAs/SM ------------------
// D[64, 256] = A[64,K] @ W[256,K]^T, fp32 accum. 256 threads, 2x4 warp grid,
// 32x64 warp tiles (identical fragment math to R14).
// MODE 0: embed | MODE 1: sage | MODE 2: link

#define SA_    0
#define SW_    8192
#define BUFSZ  40960          // A 8K + W 32K
#define S_MISC 81920
#define SMEMB  (S_MISC + 512 + 1024)

template <int MODE>
__global__ __launch_bounds__(256, 2) void gemm_tc(
    const float* __restrict__ Af, const __half* __restrict__ Ah,
    const __half* __restrict__ W1, const __half* __restrict__ W2,
    const float* __restrict__ bias, const float* __restrict__ wp2,
    __half* __restrict__ outp)
{
    extern __shared__ char smraw[];
    char* smc = (char*)(((uintptr_t)smraw + 1023) & ~(uintptr_t)1023);
    const uint32_t sbase = smem_u32(smc);
    const int tid = threadIdx.x;
    const int wid = tid >> 5, l = tid & 31;
    const int wm = wid >> 2, wn = wid & 3;       // 2 x 4 warp grid
    const int row0 = blockIdx.x * 64;

    constexpr int NCH = (MODE == 0) ? 2 : (MODE == 1) ? 8 : 16;
    constexpr int KA  = (MODE == 0) ? FEATD : (MODE == 1) ? HIDD : 1024;

    float* invd_s = (float*)(smc + S_MISC);
    if (MODE == 1 && tid < 64) {
        int row = row0 + tid;
        invd_s[tid] = (row < NN) ? 1.f / (g_deg[row] + 1.f) : 0.f;
    }
    if (MODE == 1) __syncthreads();

    float acc[2][8][4];
#pragma unroll
    for (int mt = 0; mt < 2; mt++)
#pragma unroll
        for (int nt = 0; nt < 8; nt++)
#pragma unroll
            for (int j = 0; j < 4; j++) acc[mt][nt][j] = 0.f;

    float4 phv[2];            // MODE 0 prefetch
    uint4  pqh, pqa;          // MODE 1 mean-path prefetch

    auto needs_conv = [&](int c) { return MODE == 0 || (MODE == 1 && c < 4); };

    auto issueW = [&](int c, int b) {
        const __half* W = (MODE == 1 && c >= 4) ? W2 : W1;
        const int colbase = (MODE == 1) ? ((c & 3) * 64) : (c * 64);
#pragma unroll
        for (int j = 0; j < 8; j++) {            // 2048 uint4 slots
            const int id  = j * 256 + tid;
            const int r   = id >> 3, c16 = id & 7;
            cp16(sbase + b * BUFSZ + SW_ + swz(r * 128 + c16 * 16),
                 W + (size_t)r * KA + colbase + c16 * 8);
        }
    };
    // async A (MODE 1 c>=4 from h; MODE 2 from comb): 512 uint4 slots
    auto issueA = [&](int c, int b) {
        const int colbase = (MODE == 1) ? ((c & 3) * 64) : (c * 64);
#pragma unroll
        for (int j = 0; j < 2; j++) {
            const int id  = j * 256 + tid;
            const int r   = id >> 3, c16 = id & 7;
            const uint32_t dst = sbase + b * BUFSZ + SA_ + swz(r * 128 + c16 * 16);
            if (MODE == 2 || row0 + r < NN)
                cp16(dst, Ah + (size_t)(row0 + r) * KA + colbase + c16 * 8);
            else
                *(uint4*)(smc + (dst - sbase)) = make_uint4(0u, 0u, 0u, 0u);
        }
    };
    auto loadA = [&](int c, int h) {
        const int colbase = (MODE == 1) ? ((c & 3) * 64) : (c * 64);
        if (MODE == 0) {
#pragma unroll
            for (int i = 0; i < 2; i++) {        // 1024 float4 slots over 2 halves
                const int id = (h * 2 + i) * 256 + tid;
                const int r  = id >> 4, c4 = id & 15;
                phv[i] = make_float4(0.f, 0.f, 0.f, 0.f);
                if (row0 + r < NN)
                    phv[i] = *(const float4*)(Af + (size_t)(row0 + r) * KA + colbase + c4 * 4);
            }
        } else {   // MODE 1 mean path: 512 uint4 slots over 2 halves
            const int id = h * 256 + tid;
            const int r  = id >> 3, c8 = id & 7;
            pqh = make_uint4(0u, 0u, 0u, 0u);
            pqa = make_uint4(0u, 0u, 0u, 0u);
            if (row0 + r < NN) {
                const size_t off = (size_t)(row0 + r) * HIDD + colbase + c8 * 8;
                pqh = *(const uint4*)(Ah + off);
                pqa = *(const uint4*)(g_agg + off);
            }
        }
    };
    auto storeA = [&](int c, int h, int b) {
        if (MODE == 0) {
#pragma unroll
            for (int i = 0; i < 2; i++) {
                const int id = (h * 2 + i) * 256 + tid;
                const int r  = id >> 4, c4 = id & 15;
                uint2 o;
                ((__half2*)&o)[0] = __floats2half2_rn(phv[i].x, phv[i].y);
                ((__half2*)&o)[1] = __floats2half2_rn(phv[i].z, phv[i].w);
                *(uint2*)(smc + b * BUFSZ + SA_ + swz(r * 128 + c4 * 8)) = o;
            }
        } else {
            const int id = h * 256 + tid;
            const int r  = id >> 3, c8 = id & 7;
            const float iv = invd_s[r];
            uint4 o;
            const __half2* ph = (const __half2*)&pqh;
            const __half2* pa = (const __half2*)&pqa;
            __half2* po = (__half2*)&o;
#pragma unroll
            for (int k = 0; k < 4; k++) {
                float2 hf = __half22float2(ph[k]);
                float2 af = __half22float2(pa[k]);
                po[k] = __floats2half2_rn((af.x + hf.x) * iv, (af.y + hf.y) * iv);
            }
            *(uint4*)(smc + b * BUFSZ + SA_ + swz(r * 128 + c8 * 16)) = o;
        }
    };
    auto mma2 = [&](int b, int kk0) {
        const uint32_t ab = sbase + b * BUFSZ;
#pragma unroll
        for (int kk = kk0; kk < kk0 + 2; kk++) {
            const uint32_t kbyte = kk * 32;
            uint32_t ar[2][4];
#pragma unroll
            for (int mt = 0; mt < 2; mt++) {
                uint32_t off = swz((wm * 32 + mt * 16 + (l & 15)) * 128 +
                                   kbyte + ((l >> 4) << 4));
                ldmx4(ar[mt], ab + SA_ + off);
            }
            uint32_t bf[8][2];
#pragma unroll
            for (int ntb = 0; ntb < 4; ntb++) {
                const int nt2 = ntb * 2;
                uint32_t off = swz((wn * 64 + (nt2 + ((l >> 4) & 1)) * 8 + (l & 7)) * 128
                                   + kbyte + (((l >> 3) & 1) << 4));
                uint32_t r[4];
                ldmx4(r, ab + SW_ + off);
                bf[nt2][0] = r[0]; bf[nt2][1] = r[1];
                bf[nt2 + 1][0] = r[2]; bf[nt2 + 1][1] = r[3];
            }
#pragma unroll
            for (int nt = 0; nt < 8; nt++)
#pragma unroll
                for (int mt = 0; mt < 2; mt++)
                    MMA_F16(acc[mt][nt], ar[mt], bf[nt]);
        }
    };

    // ---- prologue: chunk 0 into buffer 0 ----
    issueW(0, 0);
    if (needs_conv(0)) {
        loadA(0, 0); storeA(0, 0, 0);
        loadA(0, 1); storeA(0, 1, 0);
    } else {
        issueA(0, 0);
    }
    CP_COMMIT();
    CP_WAIT0();
    __syncthreads();

    // ---- pipelined main loop: 1 sync per chunk ----
    for (int c = 0; c < NCH; c++) {
        const int b = c & 1, nb = b ^ 1;
        const bool pf = (c + 1 < NCH);
        bool cv = pf && needs_conv(c + 1);
        if (pf) {
            issueW(c + 1, nb);
            if (cv) loadA(c + 1, 0); else issueA(c + 1, nb);
            CP_COMMIT();
        }
        mma2(b, 0);
        if (cv) { storeA(c + 1, 0, nb); loadA(c + 1, 1); }
        mma2(b, 2);
        if (cv) storeA(c + 1, 1, nb);
        CP_WAIT0();
        __syncthreads();
    }

    // ---- epilogue ----
    if (MODE == 2) {
#pragma unroll
        for (int mt = 0; mt < 2; mt++) {
            int rloc = wm * 32 + mt * 16 + (l >> 2);
            float s0 = 0.f, s1 = 0.f;
#pragma unroll
            for (int nt = 0; nt < 8; nt++) {
                int col = wn * 64 + nt * 8 + (l & 3) * 2;
                float b0 = bias[col], b1 = bias[col + 1];
                float w0 = wp2[col],  w1 = wp2[col + 1];
                s0 += fmaxf(acc[mt][nt][0] + b0, 0.f) * w0
                    + fmaxf(acc[mt][nt][1] + b1, 0.f) * w1;
                s1 += fmaxf(acc[mt][nt][2] + b0, 0.f) * w0
                    + fmaxf(acc[mt][nt][3] + b1, 0.f) * w1;
            }
            atomicAdd(&g_lacc[row0 + rloc], s0);
            atomicAdd(&g_lacc[row0 + rloc + 8], s1);
        }
    } else {
#pragma unroll
        for (int mt = 0; mt < 2; mt++) {
            int r0 = row0 + wm * 32 + mt * 16 + (l >> 2);
#pragma unroll
            for (int nt = 0; nt < 8; nt++) {
                int col = wn * 64 + nt * 8 + (l & 3) * 2;
                float b0 = bias[col], b1 = bias[col + 1];
                float v0 = acc[mt][nt][0] + b0, v1 = acc[mt][nt][1] + b1;
                float v2 = acc[mt][nt][2] + b0, v3 = acc[mt][nt][3] + b1;
                if (MODE == 1) {
                    v0 = fmaxf(v0, 0.f); v1 = fmaxf(v1, 0.f);
                    v2 = fmaxf(v2, 0.f); v3 = fmaxf(v3, 0.f);
                }
                if (r0 < NN)
                    *(__half2*)(outp + (size_t)r0 * HIDD + col) = __floats2half2_rn(v0, v1);
                if (r0 + 8 < NN)
                    *(__half2*)(outp + (size_t)(r0 + 8) * HIDD + col) = __floats2half2_rn(v2, v3);
            }
        }
    }
}

// ---------------- launcher ------------------------------------------------------
extern "C" void kernel_launch(void* const* d_in, const int* in_sizes, int n_in,
                              void* d_out, int out_size) {
    (void)in_sizes; (void)n_in; (void)out_size;
    const float* x     = (const float*)d_in[0];
    const void*  ei    = d_in[1];
    const void*  sidx  = d_in[3];
    const void*  didx  = d_in[4];
    const float* w_emb = (const float*)d_in[5];
    const float* b_emb = (const float*)d_in[6];
    const float* wl0 = (const float*)d_in[8];
    const float* bl0 = (const float*)d_in[9];
    const float* wr0 = (const float*)d_in[10];
    const float* wl1 = (const float*)d_in[13];
    const float* bl1 = (const float*)d_in[14];
    const float* wr1 = (const float*)d_in[15];
    const float* wp1 = (const float*)d_in[18];
    const float* bp1 = (const float*)d_in[19];
    const float* wp2 = (const float*)d_in[20];
    const float* bp2 = (const float*)d_in[21];
    float* out = (float*)d_out;

    cudaFuncSetAttribute(gemm_tc<0>, cudaFuncAttributeMaxDynamicSharedMemorySize, SMEMB);
    cudaFuncSetAttribute(gemm_tc<1>, cudaFuncAttributeMaxDynamicSharedMemorySize, SMEMB);
    cudaFuncSetAttribute(gemm_tc<2>, cudaFuncAttributeMaxDynamicSharedMemorySize, SMEMB);

    __half *wembC, *wl0C, *wr0C, *wl1C, *wr1C, *wp1C;
    __half *hbuf, *aggbuf, *h2buf, *combbuf;
    cudaGetSymbolAddress((void**)&wembC, g_wembC);
    cudaGetSymbolAddress((void**)&wl0C, g_wl0C);
    cudaGetSymbolAddress((void**)&wr0C, g_wr0C);
    cudaGetSymbolAddress((void**)&wl1C, g_wl1C);
    cudaGetSymbolAddress((void**)&wr1C, g_wr1C);
    cudaGetSymbolAddress((void**)&wp1C, g_wp1C);
    cudaGetSymbolAddress((void**)&hbuf, g_h);
    cudaGetSymbolAddress((void**)&aggbuf, g_agg);
    cudaGetSymbolAddress((void**)&h2buf, g_h2);
    cudaGetSymbolAddress((void**)&combbuf, g_comb);
    (void)aggbuf;

    const int zgrid = (NN * HIDD / 8 + 255) / 256;   // uint4 units of g_agg
    const int ggrid = (NN + 63) / 64;                // 1563
    const int lgrid = NL / 64;                       // 256

    prep_kernel<<<(557056 + 255) / 256, 256>>>(ei, w_emb, wl0, wr0, wl1, wr1, wp1); // 0
    zero_kernel<<<zgrid, 256>>>(1);                                                 // 1
    deg_kernel<<<(NE + 255) / 256, 256>>>(ei);                                      // 2
    gemm_tc<0><<<ggrid, 256, SMEMB>>>(x, nullptr, wembC, nullptr,
                                      b_emb, nullptr, hbuf);                        // 3
    agg_kernel<<<NE / 8, 256>>>(hbuf, ei);                                          // 4
    gemm_tc<1><<<ggrid, 256, SMEMB>>>(nullptr, hbuf, wl0C, wr0C,
                                      bl0, nullptr, h2buf);                         // 5 <- ncu
    zero_kernel<<<zgrid, 256>>>(0);                                                 // 6
    agg_kernel<<<NE / 8, 256>>>(h2buf, ei);                                         // 7
    gemm_tc<1><<<ggrid, 256, SMEMB>>>(nullptr, h2buf, wl1C, wr1C,
                                      bl1, nullptr, hbuf);                          // 8
    comb_kernel<<<NL * 32 / 256, 256>>>(hbuf, sidx, didx);                          // 9
    gemm_tc<2><<<lgrid, 256, SMEMB>>>(nullptr, combbuf, wp1C, nullptr,
                                      bp1, wp2, nullptr);                           // 10
    linkfin_kernel<<<NL / 256, 256>>>(bp2, out);                                    // 11
}